// round 13
// baseline (speedup 1.0000x reference)
#include <cuda_runtime.h>
#include <cuda_bf16.h>
#include <math.h>
#include <stdint.h>

#define BATCH 8
#define HEADS 8
#define DIM 512
#define SEQ 197
#define SEQP 208
#define NPATCH 196
#define PK 768
#define CDIM 64
#define TDIM 1576
#define NCLS 1000

// ---------------- fp32 scratch ----------------
__device__ float g_xp[BATCH*NPATCH*DIM];
__device__ float g_x[BATCH*SEQ*DIM];
__device__ float g_qkv[192*SEQ*DIM];          // [w][h][b][SEQ][DIM]
__device__ float g_sc[BATCH*HEADS*SEQ*SEQP];
__device__ float g_o[BATCH*HEADS*SEQ*DIM];
__device__ float g_ot[BATCH*SEQ*HEADS*DIM];   // proj partials [h][b][SEQ][DIM]
__device__ float g_y[BATCH*CDIM*TDIM];
__device__ float g_tqkv[24*CDIM*TDIM];        // [w][b][CDIM][TDIM]
__device__ float g_ts[BATCH*CDIM*CDIM];
__device__ float g_fac[BATCH];
__device__ float g_red[BATCH*32];
__device__ float g_cls[BATCH*DIM];
__device__ float2 g_tab1[SEQ*256];            // attention rope table [m][i]
__device__ float2 g_tab2[CDIM*788];           // token rope table [m][i]

// ---------------- bf16 hi/lo split operands (K-major) ----------------
__device__ __nv_bfloat16 g_path_h[BATCH*NPATCH*PK],  g_path_l[BATCH*NPATCH*PK];
__device__ __nv_bfloat16 g_xh[BATCH*SEQ*DIM],        g_xl[BATCH*SEQ*DIM];
__device__ __nv_bfloat16 g_qh[BATCH*HEADS*SEQ*DIM],  g_ql[BATCH*HEADS*SEQ*DIM];
__device__ __nv_bfloat16 g_kh[BATCH*HEADS*SEQ*DIM],  g_kl[BATCH*HEADS*SEQ*DIM];
__device__ __nv_bfloat16 g_ph[BATCH*HEADS*SEQ*SEQP], g_pl[BATCH*HEADS*SEQ*SEQP];
__device__ __nv_bfloat16 g_oh[BATCH*HEADS*SEQ*DIM],  g_ol[BATCH*HEADS*SEQ*DIM];
__device__ __nv_bfloat16 g_yh[BATCH*CDIM*TDIM],      g_yl[BATCH*CDIM*TDIM];
__device__ __nv_bfloat16 g_tqh[BATCH*CDIM*TDIM],     g_tql[BATCH*CDIM*TDIM];
__device__ __nv_bfloat16 g_tkh[BATCH*CDIM*TDIM],     g_tkl[BATCH*CDIM*TDIM];
__device__ __nv_bfloat16 g_tsh[BATCH*CDIM*CDIM],     g_tsl[BATCH*CDIM*CDIM];
// weights
__device__ __nv_bfloat16 g_pwh[DIM*PK],            g_pwl[DIM*PK];
__device__ __nv_bfloat16 g_wAh[2*3*8*DIM*DIM],     g_wAl[2*3*8*DIM*DIM];   // [l][w][h]
__device__ __nv_bfloat16 g_awh[16*DIM*DIM],        g_awl[16*DIM*DIM];
__device__ __nv_bfloat16 g_twAh[2*3*TDIM*TDIM],    g_twAl[2*3*TDIM*TDIM]; // [l][w]
__device__ __nv_bfloat16 g_vth[64*DIM*SEQP],       g_vtl[64*DIM*SEQP];
__device__ __nv_bfloat16 g_tvth[8*TDIM*CDIM],      g_tvtl[8*TDIM*CDIM];

// ---------------- helpers ----------------
__device__ __forceinline__ void cvt4(float4 v, uint2 &h, uint2 &l){
    __nv_bfloat16 ax=__float2bfloat16_rn(v.x), ay=__float2bfloat16_rn(v.y);
    __nv_bfloat16 az=__float2bfloat16_rn(v.z), aw=__float2bfloat16_rn(v.w);
    __nv_bfloat162 h0; h0.x=ax; h0.y=ay;
    __nv_bfloat162 h1; h1.x=az; h1.y=aw;
    h.x=*(unsigned*)&h0; h.y=*(unsigned*)&h1;
    __nv_bfloat162 l0; l0.x=__float2bfloat16_rn(v.x-__bfloat162float(ax));
                       l0.y=__float2bfloat16_rn(v.y-__bfloat162float(ay));
    __nv_bfloat162 l1; l1.x=__float2bfloat16_rn(v.z-__bfloat162float(az));
                       l1.y=__float2bfloat16_rn(v.w-__bfloat162float(aw));
    l.x=*(unsigned*)&l0; l.y=*(unsigned*)&l1;
}
__device__ __forceinline__ void cvt2(float a, float b, uint32_t &h, uint32_t &l){
    __nv_bfloat16 ha=__float2bfloat16_rn(a), hb=__float2bfloat16_rn(b);
    __nv_bfloat162 H; H.x=ha; H.y=hb; h=*(uint32_t*)&H;
    __nv_bfloat162 L; L.x=__float2bfloat16_rn(a-__bfloat162float(ha));
                      L.y=__float2bfloat16_rn(b-__bfloat162float(hb)); l=*(uint32_t*)&L;
}
__device__ __forceinline__ void cvt1(float a, __nv_bfloat16 &h, __nv_bfloat16 &l){
    h=__float2bfloat16_rn(a);
    l=__float2bfloat16_rn(a-__bfloat162float(h));
}
__device__ __forceinline__ void ldsm4(unsigned r[4], const __nv_bfloat16* p) {
    unsigned a = (unsigned)__cvta_generic_to_shared(p);
    asm volatile("ldmatrix.sync.aligned.m8n8.x4.shared.b16 {%0,%1,%2,%3}, [%4];"
                 : "=r"(r[0]), "=r"(r[1]), "=r"(r[2]), "=r"(r[3]) : "r"(a));
}
__device__ __forceinline__ void mma16816(float c[4], const unsigned a[4],
                                         unsigned b0, unsigned b1) {
    asm volatile("mma.sync.aligned.m16n8k16.row.col.f32.bf16.bf16.f32 "
                 "{%0,%1,%2,%3}, {%4,%5,%6,%7}, {%8,%9}, {%0,%1,%2,%3};"
                 : "+f"(c[0]), "+f"(c[1]), "+f"(c[2]), "+f"(c[3])
                 : "r"(a[0]), "r"(a[1]), "r"(a[2]), "r"(a[3]), "r"(b0), "r"(b1));
}
__device__ __forceinline__ void cp16(uint32_t dst, const void* src, bool valid){
    uint64_t g;
    asm("cvta.to.global.u64 %0, %1;" : "=l"(g) : "l"(src));
    int sz = valid ? 16 : 0;
    asm volatile("cp.async.cg.shared.global [%0], [%1], 16, %2;"
                 :: "r"(dst), "l"(g), "r"(sz) : "memory");
}
#define CP_COMMIT() asm volatile("cp.async.commit_group;" ::: "memory")

// ================= bf16 split GEMM: cp.async 2-stage pipeline (2 CTAs/SM) ==================
// off(z) = (z/D1)*S1 + ((z%D1)/D2)*S2 + (z%D2)*S3  for A and B independently.
template<int BM>
__global__ __launch_bounds__(BM*2)
void hgemm3(const __nv_bfloat16* __restrict__ Ah, const __nv_bfloat16* __restrict__ Al,
            const __nv_bfloat16* __restrict__ Bh, const __nv_bfloat16* __restrict__ Bl,
            const float* __restrict__ bias, const float* __restrict__ Cin,
            float* __restrict__ C,
            __nv_bfloat16* __restrict__ Ch, __nv_bfloat16* __restrict__ Cl,
            int M, int N, int K, int lda, int ldb, int ldc,
            int aD1, long long aS1, int aD2, long long aS2, long long aS3,
            int bD1, long long bS1, int bD2, long long bS2, long long bS3,
            long long sCin, long long sC, float alpha, int addC)
{
    constexpr int WARPS_M = BM/64;
    constexpr int THREADS = BM*2;
    constexpr int A_CH = BM*4/THREADS;
    constexpr int B_CH = 512/THREADS;
    constexpr int SH = (2*BM + 256)*40;      // halves per stage
    const int OFF_AL = BM*40, OFF_BH = 2*BM*40;
    extern __shared__ __align__(16) __nv_bfloat16 sm[];
    uint32_t smem_base = (uint32_t)__cvta_generic_to_shared(sm);

    int z = blockIdx.z;
    long long ao = (long long)(z / aD1)*aS1 + (long long)((z % aD1) / aD2)*aS2
                 + (long long)(z % aD2)*aS3;
    long long bo = (long long)(z / bD1)*bS1 + (long long)((z % bD1) / bD2)*bS2
                 + (long long)(z % bD2)*bS3;
    Ah += ao; Al += ao; Bh += bo; Bl += bo;
    long long co = (long long)z * sC;
    C += co;
    if (Ch){ Ch += co; Cl += co; }
    const float* Cr = addC ? Cin + (long long)z * sCin : (const float*)0;

    int row0 = blockIdx.y*BM, col0 = blockIdx.x*128;
    int tid = threadIdx.x, lane = tid & 31, warp = tid >> 5;
    int wm0 = (warp % WARPS_M)*64;
    int wn0 = (warp / WARPS_M)*32;

    float acc[4][4][4];
#pragma unroll
    for (int i=0;i<4;i++)
#pragma unroll
      for (int j=0;j<4;j++)
#pragma unroll
        for (int t=0;t<4;t++) acc[i][j][t]=0.f;

    auto issue = [&](int kt){
        int st = kt & 1;
        uint32_t sb = smem_base + st*SH*2;
        int k0 = kt*32;
#pragma unroll
        for (int t = 0; t < A_CH; t++){
            int idx = tid + t*THREADS;
            int row = idx >> 2, k8 = idx & 3;
            int gm = row0 + row, gk = k0 + k8*8;
            bool v = (gm < M) && (gk < K);
            long long go = (long long)gm*lda + gk;
            uint32_t d = sb + (uint32_t)(row*40 + k8*8)*2;
            cp16(d, v ? Ah+go : Ah, v);
            cp16(d + OFF_AL*2, v ? Al+go : Al, v);
        }
#pragma unroll
        for (int t = 0; t < B_CH; t++){
            int idx = tid + t*THREADS;
            int row = idx >> 2, k8 = idx & 3;
            int gn = col0 + row, gk = k0 + k8*8;
            bool v = (gn < N) && (gk < K);
            long long go = (long long)gn*ldb + gk;
            uint32_t d = sb + (uint32_t)(OFF_BH + row*40 + k8*8)*2;
            cp16(d, v ? Bh+go : Bh, v);
            cp16(d + 128*40*2, v ? Bl+go : Bl, v);
        }
    };

    int r8 = lane&7, s1 = (lane>>3)&1, s2 = lane>>4;
    auto compute = [&](int st, int kk){
        const __nv_bfloat16* base = sm + st*SH;
        unsigned ah[4][4], al[4][4], bh[2][4], bl[2][4];
#pragma unroll
        for (int mt=0;mt<4;mt++){
            int row = wm0 + mt*16 + r8 + s1*8;
            int col = kk + s2*8;
            ldsm4(ah[mt], base + row*40 + col);
            ldsm4(al[mt], base + OFF_AL + row*40 + col);
        }
#pragma unroll
        for (int np=0;np<2;np++){
            int row = wn0 + np*16 + r8 + s2*8;
            int col = kk + s1*8;
            ldsm4(bh[np], base + OFF_BH + row*40 + col);
            ldsm4(bl[np], base + OFF_BH + 128*40 + row*40 + col);
        }
#pragma unroll
        for (int mt=0;mt<4;mt++)
#pragma unroll
            for (int nt=0;nt<4;nt++){
                unsigned b0h = bh[nt>>1][(nt&1)*2], b1h = bh[nt>>1][(nt&1)*2+1];
                unsigned b0l = bl[nt>>1][(nt&1)*2], b1l = bl[nt>>1][(nt&1)*2+1];
                mma16816(acc[mt][nt], ah[mt], b0h, b1h);
                mma16816(acc[mt][nt], al[mt], b0h, b1h);
                mma16816(acc[mt][nt], ah[mt], b0l, b1l);
            }
    };

    int nk = (K + 31) / 32;
    issue(0); CP_COMMIT();
    for (int kt = 0; kt < nk; kt++){
        if (kt + 1 < nk){ issue(kt+1); CP_COMMIT(); }
        if (kt + 1 < nk) { asm volatile("cp.async.wait_group 1;" ::: "memory"); }
        else             { asm volatile("cp.async.wait_group 0;" ::: "memory"); }
        __syncthreads();
        int st = kt & 1;
        compute(st, 0);
        compute(st, 16);
        __syncthreads();     // stage st must be fully consumed before issue(kt+2) overwrites it
    }

    // epilogue
    int gid = lane>>2, tq = lane&3;
#pragma unroll
    for (int mt=0;mt<4;mt++)
#pragma unroll
      for (int h=0;h<2;h++){
        int gm = row0 + wm0 + mt*16 + gid + h*8;
        if (gm>=M) continue;
        long long base = (long long)gm*ldc;
#pragma unroll
        for (int nt=0;nt<4;nt++){
          int gn = col0 + wn0 + nt*8 + tq*2;
          if (gn>=N) continue;
          float v0 = alpha*acc[mt][nt][h*2+0];
          float v1 = alpha*acc[mt][nt][h*2+1];
          if (bias){ v0 += bias[gn]; if (gn+1<N) v1 += bias[gn+1]; }
          if (Cr)  { v0 += Cr[base+gn]; if (gn+1<N) v1 += Cr[base+gn+1]; }
          if (gn+1<N){
            float2 st2; st2.x=v0; st2.y=v1; *(float2*)&C[base+gn]=st2;
            if (Ch){
              uint32_t hh, ll; cvt2(v0, v1, hh, ll);
              *(uint32_t*)&Ch[base+gn] = hh;
              *(uint32_t*)&Cl[base+gn] = ll;
            }
          } else {
            C[base+gn]=v0;
            if (Ch){ __nv_bfloat16 hh, ll; cvt1(v0, hh, ll); Ch[base+gn]=hh; Cl[base+gn]=ll; }
          }
        }
      }
}

#define P_NONE  (1<<30), 0LL, 1, 0LL, 0LL
#define P_PLAIN(s) (1<<30), 0LL, 1, (long long)(s), 0LL

static void run_hgemm(const __nv_bfloat16* Ah, const __nv_bfloat16* Al,
                      const __nv_bfloat16* Bh, const __nv_bfloat16* Bl,
                      const float* bias, const float* Cin, float* C,
                      __nv_bfloat16* Ch, __nv_bfloat16* Cl,
                      int M, int N, int K, int lda, int ldb, int ldc,
                      int aD1, long long aS1, int aD2, long long aS2, long long aS3,
                      int bD1, long long bS1, int bD2, long long bS2, long long bS3,
                      long long sCin, long long sC, int batch, float alpha, int addC)
{
    long long b128 = (long long)((N+127)/128)*((M+127)/128)*batch;
    if (M >= 96 && b128 >= 90) {
        constexpr int SM = 2*(2*128+256)*40*2;   // 81920 B -> 2 CTAs/SM
        cudaFuncSetAttribute(hgemm3<128>, cudaFuncAttributeMaxDynamicSharedMemorySize, SM);
        dim3 grid((N+127)/128, (M+127)/128, batch);
        hgemm3<128><<<grid, 256, SM>>>(Ah,Al,Bh,Bl,bias,Cin,C,Ch,Cl,M,N,K,lda,ldb,ldc,
            aD1,aS1,aD2,aS2,aS3,bD1,bS1,bD2,bS2,bS3,sCin,sC,alpha,addC);
    } else {
        constexpr int SM = 2*(2*64+256)*40*2;    // 61440 B -> 3 CTAs/SM
        cudaFuncSetAttribute(hgemm3<64>, cudaFuncAttributeMaxDynamicSharedMemorySize, SM);
        dim3 grid((N+127)/128, (M+63)/64, batch);
        hgemm3<64><<<grid, 128, SM>>>(Ah,Al,Bh,Bl,bias,Cin,C,Ch,Cl,M,N,K,lda,ldb,ldc,
            aD1,aS1,aD2,aS2,aS3,bD1,bS1,bD2,bS2,bS3,sCin,sC,alpha,addC);
    }
}

// ================= transpose-convert: fp32 [K][N] -> bf16 hi/lo [N][Kp] =================
__global__ void tconv(const float* __restrict__ in, __nv_bfloat16* __restrict__ oh,
                      __nv_bfloat16* __restrict__ ol,
                      int K, int N, int Kp, long long sIn, long long sOut)
{
    __shared__ float t[32][33];
    int z = blockIdx.z;
    const float* I = in + (long long)z * sIn;
    __nv_bfloat16* OH = oh + (long long)z * sOut;
    __nv_bfloat16* OL = ol + (long long)z * sOut;
    int kb = blockIdx.y * 32, nb = blockIdx.x * 32;
    for (int i = threadIdx.y; i < 32; i += 8) {
        int k = kb + i, n = nb + threadIdx.x;
        t[i][threadIdx.x] = (k < K && n < N) ? I[(long long)k*N + n] : 0.f;
    }
    __syncthreads();
    for (int i = threadIdx.y; i < 32; i += 8) {
        int n = nb + i, k = kb + threadIdx.x;
        if (n < N && k < Kp) {
            __nv_bfloat16 h, l; cvt1(t[threadIdx.x][i], h, l);
            OH[(long long)n*Kp + k] = h;
            OL[(long long)n*Kp + k] = l;
        }
    }
}

// ---------------- fp32 fallback GEMM (final head, M=8) ----------------
__global__ __launch_bounds__(64)
void sgemm_s(const float* __restrict__ A, const float* __restrict__ B,
             const float* __restrict__ bias, float* __restrict__ C,
             int M, int N, int K, int lda, int ldb, int ldc)
{
    constexpr int BK = 16;
    __shared__ float As[BK][36];
    __shared__ float Bs[BK][36];
    int row0 = blockIdx.y*32, col0 = blockIdx.x*32;
    int tid = threadIdx.x;
    int tx = tid % 8, ty = tid / 8;
    float acc[4][4];
#pragma unroll
    for (int i=0;i<4;i++)
#pragma unroll
      for (int j=0;j<4;j++) acc[i][j]=0.f;
    for (int k0 = 0; k0 < K; k0 += BK) {
        for (int e = tid; e < 32*BK/4; e += 64) {
            int mm = e >> 2, c4 = e & 3;
            int gm = row0+mm, gk = k0+c4*4;
            float4 v = make_float4(0.f,0.f,0.f,0.f);
            if (gm < M && gk < K) v = *(const float4*)&A[(long long)gm*lda+gk];
            As[c4*4+0][mm]=v.x; As[c4*4+1][mm]=v.y; As[c4*4+2][mm]=v.z; As[c4*4+3][mm]=v.w;
        }
        for (int e = tid; e < BK*8; e += 64) {
            int kk = e / 8, n4 = e % 8;
            int gk = k0+kk, gn = col0+n4*4;
            float4 v = make_float4(0.f,0.f,0.f,0.f);
            if (gk < K) {
                if (gn+3 < N) v = *(const float4*)&B[(long long)gk*ldb+gn];
                else {
                    const float* p = &B[(long long)gk*ldb];
                    if (gn<N)v.x=p[gn]; if (gn+1<N)v.y=p[gn+1];
                    if (gn+2<N)v.z=p[gn+2]; if (gn+3<N)v.w=p[gn+3];
                }
            }
            Bs[kk][n4*4+0]=v.x; Bs[kk][n4*4+1]=v.y; Bs[kk][n4*4+2]=v.z; Bs[kk][n4*4+3]=v.w;
        }
        __syncthreads();
#pragma unroll
        for (int kk = 0; kk < BK; kk++) {
            float a[4], b[4];
#pragma unroll
            for (int i=0;i<4;i++) a[i]=As[kk][ty*4+i];
#pragma unroll
            for (int j=0;j<4;j++) b[j]=Bs[kk][tx*4+j];
#pragma unroll
            for (int i=0;i<4;i++)
#pragma unroll
              for (int j=0;j<4;j++) acc[i][j]+=a[i]*b[j];
        }
        __syncthreads();
    }
#pragma unroll
    for (int i=0;i<4;i++){
        int gm = row0+ty*4+i;
        if (gm >= M) continue;
#pragma unroll
        for (int j=0;j<4;j++){
            int gn = col0+tx*4+j;
            if (gn >= N) continue;
            float v = acc[i][j];
            if (bias) v += bias[gn];
            C[(long long)gm*ldc+gn] = v;
        }
    }
}

// ---------------- elementwise kernels ----------------
__global__ void patch_gather2(const float* __restrict__ img,
                              __nv_bfloat16* __restrict__ oh, __nv_bfloat16* __restrict__ ol) {
    int idx = blockIdx.x*blockDim.x + threadIdx.x;
    int total = BATCH*NPATCH*PK;
    if (idx >= total) return;
    int k = idx % PK;
    int p = (idx / PK) % NPATCH;
    int b = idx / (PK*NPATCH);
    int c  = k % 3;
    int pj = (k/3) % 16;
    int pi = k / 48;
    int i = p / 14, j = p % 14;
    float v = img[(((long long)b*3 + c)*224 + (i*16+pi))*224 + (j*16+pj)];
    __nv_bfloat16 h, l; cvt1(v, h, l);
    oh[idx] = h; ol[idx] = l;
}

__global__ void assemble_x_kernel(const float* __restrict__ xp, const float* __restrict__ cls,
                                  float* __restrict__ x) {
    int idx = blockIdx.x*blockDim.x + threadIdx.x;
    int total = BATCH*SEQ*DIM;
    if (idx >= total) return;
    int d = idx % DIM;
    int m = (idx / DIM) % SEQ;
    int b = idx / (DIM*SEQ);
    x[idx] = (m == 0) ? cls[d] : xp[((long long)b*NPATCH + (m-1))*DIM + d];
}

__global__ void rms_part_kernel(const float* __restrict__ x, float* __restrict__ red) {
    int b = blockIdx.y, ch = blockIdx.x;
    const int per_batch = SEQ*DIM;
    const int chunk = per_batch/32;
    const float4* p = (const float4*)(x + (long long)b*per_batch + ch*chunk);
    float s = 0.f;
    for (int i = threadIdx.x; i < chunk/4; i += 256) {
        float4 v = p[i];
        s += v.x*v.x + v.y*v.y + v.z*v.z + v.w*v.w;
    }
    __shared__ float sm[256];
    sm[threadIdx.x] = s; __syncthreads();
    for (int o = 128; o > 0; o >>= 1) { if (threadIdx.x < o) sm[threadIdx.x] += sm[threadIdx.x+o]; __syncthreads(); }
    if (threadIdx.x == 0) red[b*32 + ch] = sm[0];
}
__global__ void rms_fin_kernel(const float* __restrict__ red, float* __restrict__ fac) {
    int b = threadIdx.x / 32, lane = threadIdx.x % 32;
    float v = red[b*32 + lane];
    for (int o = 16; o; o >>= 1) v += __shfl_xor_sync(0xffffffffu, v, o);
    if (lane == 0) fac[b] = sqrtf((float)(SEQ*DIM) / v);
}
__global__ void rms_apply2(float* __restrict__ x, const float* __restrict__ fac,
                           const float* __restrict__ scale,
                           uint2* __restrict__ xh, uint2* __restrict__ xl) {
    int idx = blockIdx.x*blockDim.x + threadIdx.x;
    const int per4 = SEQ*DIM/4;
    int total = BATCH*per4;
    if (idx >= total) return;
    int b = idx / per4, s4 = idx % per4;
    float f = fac[b];
    float4 v = ((float4*)x)[idx];
    float4 sc = ((const float4*)scale)[s4];
    v.x *= f*sc.x; v.y *= f*sc.y; v.z *= f*sc.z; v.w *= f*sc.w;
    ((float4*)x)[idx] = v;
    uint2 h, l; cvt4(v, h, l);
    xh[idx] = h; xl[idx] = l;
}

// rope table: identical per-element float ops as before (bit-identical values)
__global__ void rope_tab(float2* __restrict__ tab, int M, int half, float cc) {
    int idx = blockIdx.x*blockDim.x + threadIdx.x;
    if (idx >= M*half) return;
    int i = idx % half, m = idx / half;
    float theta = exp2f(cc * ((float)i - 1.f));
    float ang = (float)m * theta;
    float s, c;
    sincosf(ang, &s, &c);
    tab[idx] = make_float2(c, s);
}

__global__ void rope3(const float* __restrict__ q, const float* __restrict__ k,
                      __nv_bfloat16* __restrict__ qh, __nv_bfloat16* __restrict__ ql,
                      __nv_bfloat16* __restrict__ kh, __nv_bfloat16* __restrict__ kl,
                      const float2* __restrict__ tab, int Z, int M, int D) {
    int half = D / 2;
    long long total = (long long)Z * M * half;
    long long idx = (long long)blockIdx.x*blockDim.x + threadIdx.x;
    if (idx >= total) return;
    int i = (int)(idx % half);
    int m = (int)((idx / half) % M);
    long long z = idx / ((long long)half * M);
    float2 cs = tab[m*half + i];
    float c = cs.x, s = cs.y;
    long long base = ((z*M) + m) * (long long)D + 2*i;
    float xe, xo, re, ro;
    uint32_t h, l;
    xe = q[base]; xo = q[base+1];
    re = xe*c + xo*s; ro = -xe*s + xo*c;
    cvt2(re, ro, h, l);
    *(uint32_t*)&qh[base] = h; *(uint32_t*)&ql[base] = l;
    xe = k[base]; xo = k[base+1];
    re = xe*c + xo*s; ro = -xe*s + xo*c;
    cvt2(re, ro, h, l);
    *(uint32_t*)&kh[base] = h; *(uint32_t*)&kl[base] = l;
}

__global__ void softmax2(float* __restrict__ s,
                         __nv_bfloat16* __restrict__ ph, __nv_bfloat16* __restrict__ pl,
                         int rows, int L, int ld) {
    int warp = (blockIdx.x*blockDim.x + threadIdx.x) / 32;
    int lane = threadIdx.x % 32;
    if (warp >= rows) return;
    long long ro = (long long)warp * ld;
    float* row = s + ro;
    float mx = -1e30f;
    for (int i = lane; i < L; i += 32) mx = fmaxf(mx, row[i]);
    for (int o = 16; o; o >>= 1) mx = fmaxf(mx, __shfl_xor_sync(0xffffffffu, mx, o));
    float sum = 0.f;
    for (int i = lane; i < L; i += 32) { float e = __expf(row[i]-mx); row[i] = e; sum += e; }
    for (int o = 16; o; o >>= 1) sum += __shfl_xor_sync(0xffffffffu, sum, o);
    float inv = 1.f / sum;
    for (int i = lane; i < ld; i += 32) {
        float v = (i < L) ? row[i]*inv : 0.f;
        __nv_bfloat16 h, l; cvt1(v, h, l);
        ph[ro + i] = h; pl[ro + i] = l;
    }
}

// x[b][m][:] += bias + sum_h part[(h*8+b)][m][:]   ([h][b] slice order)
__global__ void attn_reduce_kernel(const float* __restrict__ part,
                                   const float* __restrict__ bias,
                                   float* __restrict__ x) {
    int idx = blockIdx.x*blockDim.x + threadIdx.x;
    const int D4 = DIM/4;
    int total = BATCH*SEQ*D4;
    if (idx >= total) return;
    int d4 = idx % D4;
    int m  = (idx / D4) % SEQ;
    int b  = idx / (D4*SEQ);
    float4 acc = ((float4*)x)[idx];
    float4 bb = ((const float4*)bias)[d4];
    acc.x += bb.x; acc.y += bb.y; acc.z += bb.z; acc.w += bb.w;
#pragma unroll
    for (int h = 0; h < HEADS; h++) {
        float4 p = ((const float4*)part)[((long long)(h*BATCH+b)*SEQ + m)*D4 + d4];
        acc.x += p.x; acc.y += p.y; acc.z += p.z; acc.w += p.w;
    }
    ((float4*)x)[idx] = acc;
}

__global__ void x_to_y2(const float* __restrict__ x, float* __restrict__ y,
                        __nv_bfloat16* __restrict__ yh, __nv_bfloat16* __restrict__ yl) {
    int idx = blockIdx.x*blockDim.x + threadIdx.x;
    int total = BATCH*CDIM*TDIM;
    if (idx >= total) return;
    int t = idx % TDIM;
    int c = (idx / TDIM) % CDIM;
    int b = idx / (TDIM*CDIM);
    int f = t / SEQ, mm = t % SEQ;
    float v = x[((long long)b*SEQ + mm)*DIM + c*8 + f];
    y[idx] = v;
    __nv_bfloat16 h, l; cvt1(v, h, l);
    yh[idx] = h; yl[idx] = l;
}

__global__ void y_to_x_kernel(const float* __restrict__ y, float* __restrict__ x) {
    int idx = blockIdx.x*blockDim.x + threadIdx.x;
    int total = BATCH*SEQ*DIM;
    if (idx >= total) return;
    int d  = idx % DIM;
    int mm = (idx / DIM) % SEQ;
    int b  = idx / (DIM*SEQ);
    int c = d >> 3, f = d & 7;
    x[idx] = y[((long long)b*CDIM + c)*TDIM + f*SEQ + mm];
}

__global__ void cls_ln_kernel(const float* __restrict__ x, const float* __restrict__ g,
                              const float* __restrict__ be, float* __restrict__ out) {
    int b = blockIdx.x, t = threadIdx.x;
    const float* row = x + (long long)b*SEQ*DIM;
    __shared__ float red[256];
    float s = 0.f;
    for (int i = t; i < DIM; i += 256) s += row[i];
    red[t] = s; __syncthreads();
    for (int o = 128; o > 0; o >>= 1) { if (t < o) red[t] += red[t+o]; __syncthreads(); }
    float mu = red[0] / DIM; __syncthreads();
    float v = 0.f;
    for (int i = t; i < DIM; i += 256) { float d = row[i]-mu; v += d*d; }
    red[t] = v; __syncthreads();
    for (int o = 128; o > 0; o >>= 1) { if (t < o) red[t] += red[t+o]; __syncthreads(); }
    float inv = rsqrtf(red[0]/DIM + 1e-5f);
    for (int i = t; i < DIM; i += 256) out[b*DIM + i] = (row[i]-mu)*inv*g[i] + be[i];
}

static inline int nblk(long long n, int t) { return (int)((n + t - 1) / t); }

extern "C" void kernel_launch(void* const* d_in, const int* in_sizes, int n_in,
                              void* d_out, int out_size) {
    const float* img       = (const float*)d_in[0];
    const float* patch_W   = (const float*)d_in[1];
    const float* patch_b   = (const float*)d_in[2];
    const float* cls_token = (const float*)d_in[3];
    const float* rms_scale = (const float*)d_in[4];
    const float* Wq        = (const float*)d_in[5];
    const float* Wk        = (const float*)d_in[6];
    const float* Wv        = (const float*)d_in[7];
    const float* attn_W    = (const float*)d_in[8];
    const float* attn_b    = (const float*)d_in[9];
    const float* tWq       = (const float*)d_in[10];
    const float* tWk       = (const float*)d_in[11];
    const float* tWv       = (const float*)d_in[12];
    const float* ln_g      = (const float*)d_in[13];
    const float* ln_b      = (const float*)d_in[14];
    const float* head_W    = (const float*)d_in[15];
    const float* head_b    = (const float*)d_in[16];
    float* out = (float*)d_out;

    float *pxp,*px,*pqkv,*ps,*po,*pot,*py,*ptqkv,*pts,*pf,*pred,*pcls;
    float2 *ptab1,*ptab2;
    cudaGetSymbolAddress((void**)&pxp,  g_xp);
    cudaGetSymbolAddress((void**)&px,   g_x);
    cudaGetSymbolAddress((void**)&pqkv, g_qkv);
    cudaGetSymbolAddress((void**)&ps,   g_sc);
    cudaGetSymbolAddress((void**)&po,   g_o);
    cudaGetSymbolAddress((void**)&pot,  g_ot);
    cudaGetSymbolAddress((void**)&py,   g_y);
    cudaGetSymbolAddress((void**)&ptqkv,g_tqkv);
    cudaGetSymbolAddress((void**)&pts,  g_ts);
    cudaGetSymbolAddress((void**)&pf,   g_fac);
    cudaGetSymbolAddress((void**)&pred, g_red);
    cudaGetSymbolAddress((void**)&pcls, g_cls);
    cudaGetSymbolAddress((void**)&ptab1, g_tab1);
    cudaGetSymbolAddress((void**)&ptab2, g_tab2);

    __nv_bfloat16 *path_h,*path_l,*xh,*xl,*qh,*ql,*kh,*kl,*ph,*pl,*oh,*ol;
    __nv_bfloat16 *yh,*yl,*tqh,*tql,*tkh,*tkl,*tsh,*tsl;
    __nv_bfloat16 *pwh,*pwl,*wAh,*wAl,*awh,*awl,*twAh,*twAl,*vth,*vtl,*tvth,*tvtl;
    cudaGetSymbolAddress((void**)&path_h, g_path_h); cudaGetSymbolAddress((void**)&path_l, g_path_l);
    cudaGetSymbolAddress((void**)&xh,  g_xh);  cudaGetSymbolAddress((void**)&xl,  g_xl);
    cudaGetSymbolAddress((void**)&qh,  g_qh);  cudaGetSymbolAddress((void**)&ql,  g_ql);
    cudaGetSymbolAddress((void**)&kh,  g_kh);  cudaGetSymbolAddress((void**)&kl,  g_kl);
    cudaGetSymbolAddress((void**)&ph,  g_ph);  cudaGetSymbolAddress((void**)&pl,  g_pl);
    cudaGetSymbolAddress((void**)&oh,  g_oh);  cudaGetSymbolAddress((void**)&ol,  g_ol);
    cudaGetSymbolAddress((void**)&yh,  g_yh);  cudaGetSymbolAddress((void**)&yl,  g_yl);
    cudaGetSymbolAddress((void**)&tqh, g_tqh); cudaGetSymbolAddress((void**)&tql, g_tql);
    cudaGetSymbolAddress((void**)&tkh, g_tkh); cudaGetSymbolAddress((void**)&tkl, g_tkl);
    cudaGetSymbolAddress((void**)&tsh, g_tsh); cudaGetSymbolAddress((void**)&tsl, g_tsl);
    cudaGetSymbolAddress((void**)&pwh,  g_pwh);  cudaGetSymbolAddress((void**)&pwl,  g_pwl);
    cudaGetSymbolAddress((void**)&wAh,  g_wAh);  cudaGetSymbolAddress((void**)&wAl,  g_wAl);
    cudaGetSymbolAddress((void**)&awh,  g_awh);  cudaGetSymbolAddress((void**)&awl,  g_awl);
    cudaGetSymbolAddress((void**)&twAh, g_twAh); cudaGetSymbolAddress((void**)&twAl, g_twAl);
    cudaGetSymbolAddress((void**)&vth,  g_vth);  cudaGetSymbolAddress((void**)&vtl,  g_vtl);
    cudaGetSymbolAddress((void**)&tvth, g_tvth); cudaGetSymbolAddress((void**)&tvtl, g_tvtl);

    const long long sQH  = (long long)SEQ*DIM;
    const long long sSSp = (long long)SEQ*SEQP;
    const long long sY   = (long long)CDIM*TDIM;
    const long long sTS  = (long long)CDIM*CDIM;
    const long long sW   = (long long)DIM*DIM;
    const long long sVT  = (long long)DIM*SEQP;
    const long long sTVT = (long long)TDIM*CDIM;
    const long long sTW  = (long long)TDIM*TDIM;
    const float scale1 = (float)(1.0/sqrt(512.0));
    const float scale2 = (float)(1.0/sqrt(1576.0));
    const float cc1 = (float)(-2.0*log2(10000.0)/512.0);
    const float cc2 = (float)(-2.0*log2(10000.0)/1576.0);
    dim3 tcb(32, 8);

    // ---- rope tables (layer-independent) ----
    rope_tab<<<nblk(SEQ*256,256),256>>>(ptab1, SEQ, 256, cc1);
    rope_tab<<<nblk(CDIM*788,256),256>>>(ptab2, CDIM, 788, cc2);

    // ---- weight pre-conversion into combined buffers ----
    tconv<<<dim3(DIM/32, PK/32, 1), tcb>>>(patch_W, pwh, pwl, PK, DIM, PK, 0, 0);
    for (int l = 0; l < 2; l++) {
        const float* srcs[3] = {Wq, Wk, Wv};
        for (int w = 0; w < 3; w++) {
            tconv<<<dim3(16, 16, 8), tcb>>>(srcs[w] + (long long)l*8*sW,
                                            wAh + ((long long)l*24 + w*8)*sW,
                                            wAl + ((long long)l*24 + w*8)*sW,
                                            DIM, DIM, DIM, sW, sW);
        }
        const float* tsrcs[3] = {tWq, tWk, tWv};
        for (int w = 0; w < 3; w++) {
            tconv<<<dim3(50, 50, 1), tcb>>>(tsrcs[w] + (long long)l*sTW,
                                            twAh + ((long long)l*3 + w)*sTW,
                                            twAl + ((long long)l*3 + w)*sTW,
                                            TDIM, TDIM, TDIM, 0, 0);
        }
    }
    tconv<<<dim3(16, 16, 16), tcb>>>(attn_W, awh, awl, DIM, DIM, DIM, sW, sW);

    // ---- patch embedding ----
    patch_gather2<<<nblk((long long)BATCH*NPATCH*PK,256),256>>>(img, path_h, path_l);
    run_hgemm(path_h, path_l, pwh, pwl, patch_b, 0, pxp, 0, 0,
              BATCH*NPATCH, DIM, PK, PK, PK, DIM,
              P_NONE, P_NONE, 0, 0, 1, 1.f, 0);
    assemble_x_kernel<<<nblk((long long)BATCH*SEQ*DIM,256),256>>>(pxp, cls_token, px);

    for (int l = 0; l < 2; l++) {
        const float* scale_l = rms_scale + (long long)l*SEQ*DIM;

        // rmsnorm #1 (+split)
        rms_part_kernel<<<dim3(32,BATCH),256>>>(px, pred);
        rms_fin_kernel<<<1,256>>>(pred, pf);
        rms_apply2<<<nblk((long long)BATCH*SEQ*DIM/4,256),256>>>(px, pf, scale_l,
                                                                 (uint2*)xh, (uint2*)xl);

        // fused QKV, batch folded into M: M=1576, z = w*8+h (24 batches)
        run_hgemm(xh, xl, wAh + (long long)l*24*sW, wAl + (long long)l*24*sW, 0, 0, pqkv, 0, 0,
                  BATCH*SEQ, DIM, DIM, DIM, DIM, DIM,
                  P_NONE,
                  8, 8*sW, 8, 0LL, sW,
                  0, 8*sQH, 24, 1.f, 0);

        // v -> vT split [DIM][SEQP]
        tconv<<<dim3(16, 7, 64), tcb>>>(pqkv + 128*sQH, vth, vtl, SEQ, DIM, SEQP, sQH, sVT);

        // RoPE -> split q,k (table-driven)
        rope3<<<nblk((long long)64*SEQ*(DIM/2),256),256>>>(pqkv, pqkv + 64*sQH,
                                                           qh, ql, kh, kl, ptab1, 64, SEQ, DIM);

        // scores
        run_hgemm(qh, ql, kh, kl, 0, 0, ps, 0, 0,
                  SEQ, SEQ, DIM, DIM, DIM, SEQP,
                  P_PLAIN(sQH), P_PLAIN(sQH), 0, sSSp, 64, scale1, 0);
        softmax2<<<nblk((long long)64*SEQ*32,256),256>>>(ps, ph, pl, 64*SEQ, SEQ, SEQP);

        // o = p @ v (epilogue emits split oh/ol)
        run_hgemm(ph, pl, vth, vtl, 0, 0, po, oh, ol,
                  SEQ, DIM, SEQP, SEQP, SEQP, DIM,
                  P_PLAIN(sSSp), P_PLAIN(sVT), 0, sQH, 64, 1.f, 0);

        // proj partials, batch folded into M: M=1576, z=h (8 batches)
        run_hgemm(oh, ol, awh + (long long)l*8*sW, awl + (long long)l*8*sW, 0, 0, pot, 0, 0,
                  BATCH*SEQ, DIM, DIM, DIM, DIM, DIM,
                  P_PLAIN(8*sQH), P_PLAIN(sW), 0, 8*sQH, 8, 1.f, 0);
        attn_reduce_kernel<<<nblk((long long)BATCH*SEQ*DIM/4,256),256>>>(pot, attn_b + l*DIM, px);

        // rmsnorm #2 (+split)
        rms_part_kernel<<<dim3(32,BATCH),256>>>(px, pred);
        rms_fin_kernel<<<1,256>>>(pred, pf);
        rms_apply2<<<nblk((long long)BATCH*SEQ*DIM/4,256),256>>>(px, pf, scale_l,
                                                                 (uint2*)xh, (uint2*)xl);

        // token-mixing
        x_to_y2<<<nblk((long long)BATCH*CDIM*TDIM,256),256>>>(px, py, yh, yl);

        // fused token QKV, batch folded into M: M=512, z=w (3 batches)
        run_hgemm(yh, yl, twAh + (long long)l*3*sTW, twAl + (long long)l*3*sTW, 0, 0, ptqkv, 0, 0,
                  BATCH*CDIM, TDIM, TDIM, TDIM, TDIM, TDIM,
                  P_NONE, P_PLAIN(sTW), 0, 8*sY, 3, 1.f, 0);

        // tv -> tvT split
        tconv<<<dim3(50, 2, 8), tcb>>>(ptqkv + 16*sY, tvth, tvtl, CDIM, TDIM, CDIM, sY, sTVT);

        // RoPE -> split tq,tk (table-driven)
        rope3<<<nblk((long long)BATCH*CDIM*(TDIM/2),256),256>>>(ptqkv, ptqkv + 8*sY,
                                                                 tqh, tql, tkh, tkl,
                                                                 ptab2, BATCH, CDIM, TDIM);

        // token scores
        run_hgemm(tqh, tql, tkh, tkl, 0, 0, pts, 0, 0,
                  CDIM, CDIM, TDIM, TDIM, TDIM, CDIM,
                  P_PLAIN(sY), P_PLAIN(sY), 0, sTS, BATCH, scale2, 0);
        softmax2<<<nblk((long long)BATCH*CDIM*32,256),256>>>(pts, tsh, tsl,
                                                             BATCH*CDIM, CDIM, CDIM);

        // y += p @ tv
        run_hgemm(tsh, tsl, tvth, tvtl, 0, py, py, 0, 0,
                  CDIM, TDIM, CDIM, CDIM, CDIM, TDIM,
                  P_PLAIN(sTS), P_PLAIN(sTVT), sY, sY, BATCH, 1.f, 1);

        y_to_x_kernel<<<nblk((long long)BATCH*SEQ*DIM,256),256>>>(py, px);
    }

    // ---- final: cls layernorm + head ----
    cls_ln_kernel<<<BATCH,256>>>(px, ln_g, ln_b, pcls);
    {
        dim3 grid((NCLS+31)/32, 1, 1);
        sgemm_s<<<grid, 64>>>(pcls, head_W, head_b, out, BATCH, NCLS, DIM, DIM, NCLS, NCLS);
    }
}

// round 14
// speedup vs baseline: 1.5667x; 1.5667x over previous
#include <cuda_runtime.h>
#include <cuda_bf16.h>
#include <math.h>
#include <stdint.h>

#define BATCH 8
#define HEADS 8
#define DIM 512
#define SEQ 197
#define SEQP 208
#define NPATCH 196
#define PK 768
#define CDIM 64
#define TDIM 1576
#define NCLS 1000

// ---------------- fp32 scratch ----------------
__device__ float g_xp[BATCH*NPATCH*DIM];
__device__ float g_x[BATCH*SEQ*DIM];
__device__ float g_qkv[192*SEQ*DIM];          // [w][h][b][SEQ][DIM]
__device__ float g_sc[BATCH*HEADS*SEQ*SEQP];
__device__ float g_o[BATCH*HEADS*SEQ*DIM];
__device__ float g_ot[BATCH*SEQ*HEADS*DIM];   // proj partials [h][b][SEQ][DIM]
__device__ float g_y[BATCH*CDIM*TDIM];
__device__ float g_tqkv[24*CDIM*TDIM];        // [w][b][CDIM][TDIM]
__device__ float g_ts[BATCH*CDIM*CDIM];
__device__ float g_fac[BATCH];
__device__ float g_red[BATCH*32];
__device__ float g_cls[BATCH*DIM];
__device__ float2 g_tab1[SEQ*256];            // attention rope table [m][i]
__device__ float2 g_tab2[CDIM*788];           // token rope table [m][i]

// ---------------- bf16 hi/lo split operands (K-major) ----------------
__device__ __nv_bfloat16 g_path_h[BATCH*NPATCH*PK],  g_path_l[BATCH*NPATCH*PK];
__device__ __nv_bfloat16 g_xh[BATCH*SEQ*DIM],        g_xl[BATCH*SEQ*DIM];
__device__ __nv_bfloat16 g_qh[BATCH*HEADS*SEQ*DIM],  g_ql[BATCH*HEADS*SEQ*DIM];
__device__ __nv_bfloat16 g_kh[BATCH*HEADS*SEQ*DIM],  g_kl[BATCH*HEADS*SEQ*DIM];
__device__ __nv_bfloat16 g_ph[BATCH*HEADS*SEQ*SEQP], g_pl[BATCH*HEADS*SEQ*SEQP];
__device__ __nv_bfloat16 g_oh[BATCH*HEADS*SEQ*DIM],  g_ol[BATCH*HEADS*SEQ*DIM];
__device__ __nv_bfloat16 g_yh[BATCH*CDIM*TDIM],      g_yl[BATCH*CDIM*TDIM];
__device__ __nv_bfloat16 g_tqh[BATCH*CDIM*TDIM],     g_tql[BATCH*CDIM*TDIM];
__device__ __nv_bfloat16 g_tkh[BATCH*CDIM*TDIM],     g_tkl[BATCH*CDIM*TDIM];
__device__ __nv_bfloat16 g_tsh[BATCH*CDIM*CDIM],     g_tsl[BATCH*CDIM*CDIM];
// weights
__device__ __nv_bfloat16 g_pwh[DIM*PK],            g_pwl[DIM*PK];
__device__ __nv_bfloat16 g_wAh[2*3*8*DIM*DIM],     g_wAl[2*3*8*DIM*DIM];   // [l][w][h]
__device__ __nv_bfloat16 g_awh[16*DIM*DIM],        g_awl[16*DIM*DIM];
__device__ __nv_bfloat16 g_twAh[2*3*TDIM*TDIM],    g_twAl[2*3*TDIM*TDIM]; // [l][w]
__device__ __nv_bfloat16 g_vth[64*DIM*SEQP],       g_vtl[64*DIM*SEQP];
__device__ __nv_bfloat16 g_tvth[8*TDIM*CDIM],      g_tvtl[8*TDIM*CDIM];

// ---------------- helpers ----------------
__device__ __forceinline__ void cvt4(float4 v, uint2 &h, uint2 &l){
    __nv_bfloat16 ax=__float2bfloat16_rn(v.x), ay=__float2bfloat16_rn(v.y);
    __nv_bfloat16 az=__float2bfloat16_rn(v.z), aw=__float2bfloat16_rn(v.w);
    __nv_bfloat162 h0; h0.x=ax; h0.y=ay;
    __nv_bfloat162 h1; h1.x=az; h1.y=aw;
    h.x=*(unsigned*)&h0; h.y=*(unsigned*)&h1;
    __nv_bfloat162 l0; l0.x=__float2bfloat16_rn(v.x-__bfloat162float(ax));
                       l0.y=__float2bfloat16_rn(v.y-__bfloat162float(ay));
    __nv_bfloat162 l1; l1.x=__float2bfloat16_rn(v.z-__bfloat162float(az));
                       l1.y=__float2bfloat16_rn(v.w-__bfloat162float(aw));
    l.x=*(unsigned*)&l0; l.y=*(unsigned*)&l1;
}
__device__ __forceinline__ void cvt2(float a, float b, uint32_t &h, uint32_t &l){
    __nv_bfloat16 ha=__float2bfloat16_rn(a), hb=__float2bfloat16_rn(b);
    __nv_bfloat162 H; H.x=ha; H.y=hb; h=*(uint32_t*)&H;
    __nv_bfloat162 L; L.x=__float2bfloat16_rn(a-__bfloat162float(ha));
                      L.y=__float2bfloat16_rn(b-__bfloat162float(hb)); l=*(uint32_t*)&L;
}
__device__ __forceinline__ void cvt1(float a, __nv_bfloat16 &h, __nv_bfloat16 &l){
    h=__float2bfloat16_rn(a);
    l=__float2bfloat16_rn(a-__bfloat162float(h));
}
__device__ __forceinline__ void ldsm4(unsigned r[4], const __nv_bfloat16* p) {
    unsigned a = (unsigned)__cvta_generic_to_shared(p);
    asm volatile("ldmatrix.sync.aligned.m8n8.x4.shared.b16 {%0,%1,%2,%3}, [%4];"
                 : "=r"(r[0]), "=r"(r[1]), "=r"(r[2]), "=r"(r[3]) : "r"(a));
}
__device__ __forceinline__ void mma16816(float c[4], const unsigned a[4],
                                         unsigned b0, unsigned b1) {
    asm volatile("mma.sync.aligned.m16n8k16.row.col.f32.bf16.bf16.f32 "
                 "{%0,%1,%2,%3}, {%4,%5,%6,%7}, {%8,%9}, {%0,%1,%2,%3};"
                 : "+f"(c[0]), "+f"(c[1]), "+f"(c[2]), "+f"(c[3])
                 : "r"(a[0]), "r"(a[1]), "r"(a[2]), "r"(a[3]), "r"(b0), "r"(b1));
}
__device__ __forceinline__ void cp16(uint32_t dst, const void* src, bool valid){
    uint64_t g;
    asm("cvta.to.global.u64 %0, %1;" : "=l"(g) : "l"(src));
    int sz = valid ? 16 : 0;
    asm volatile("cp.async.cg.shared.global [%0], [%1], 16, %2;"
                 :: "r"(dst), "l"(g), "r"(sz) : "memory");
}
#define CP_COMMIT() asm volatile("cp.async.commit_group;" ::: "memory")

// ================= bf16 split GEMM: cp.async 3-stage pipeline (R12-proven) ==================
// off(z) = (z/D1)*S1 + ((z%D1)/D2)*S2 + (z%D2)*S3  for A and B independently.
template<int BM>
__global__ __launch_bounds__(BM*2)
void hgemm3(const __nv_bfloat16* __restrict__ Ah, const __nv_bfloat16* __restrict__ Al,
            const __nv_bfloat16* __restrict__ Bh, const __nv_bfloat16* __restrict__ Bl,
            const float* __restrict__ bias, const float* __restrict__ Cin,
            float* __restrict__ C,
            __nv_bfloat16* __restrict__ Ch, __nv_bfloat16* __restrict__ Cl,
            int M, int N, int K, int lda, int ldb, int ldc,
            int aD1, long long aS1, int aD2, long long aS2, long long aS3,
            int bD1, long long bS1, int bD2, long long bS2, long long bS3,
            long long sCin, long long sC, float alpha, int addC)
{
    constexpr int WARPS_M = BM/64;
    constexpr int THREADS = BM*2;
    constexpr int A_CH = BM*4/THREADS;       // 16B chunks per thread (A hi)
    constexpr int B_CH = 512/THREADS;        // 16B chunks per thread (B hi)
    constexpr int SH = (2*BM + 256)*40;      // halves per stage
    const int OFF_AL = BM*40, OFF_BH = 2*BM*40;
    extern __shared__ __align__(16) __nv_bfloat16 sm[];
    uint32_t smem_base = (uint32_t)__cvta_generic_to_shared(sm);

    int z = blockIdx.z;
    long long ao = (long long)(z / aD1)*aS1 + (long long)((z % aD1) / aD2)*aS2
                 + (long long)(z % aD2)*aS3;
    long long bo = (long long)(z / bD1)*bS1 + (long long)((z % bD1) / bD2)*bS2
                 + (long long)(z % bD2)*bS3;
    Ah += ao; Al += ao; Bh += bo; Bl += bo;
    long long co = (long long)z * sC;
    C += co;
    if (Ch){ Ch += co; Cl += co; }
    const float* Cr = addC ? Cin + (long long)z * sCin : (const float*)0;

    int row0 = blockIdx.y*BM, col0 = blockIdx.x*128;
    int tid = threadIdx.x, lane = tid & 31, warp = tid >> 5;
    int wm0 = (warp % WARPS_M)*64;
    int wn0 = (warp / WARPS_M)*32;

    float acc[4][4][4];
#pragma unroll
    for (int i=0;i<4;i++)
#pragma unroll
      for (int j=0;j<4;j++)
#pragma unroll
        for (int t=0;t<4;t++) acc[i][j][t]=0.f;

    auto issue = [&](int kt){
        int st = kt % 3;
        uint32_t sb = smem_base + st*SH*2;
        int k0 = kt*32;
#pragma unroll
        for (int t = 0; t < A_CH; t++){
            int idx = tid + t*THREADS;
            int row = idx >> 2, k8 = idx & 3;
            int gm = row0 + row, gk = k0 + k8*8;
            bool v = (gm < M) && (gk < K);
            long long go = (long long)gm*lda + gk;
            uint32_t d = sb + (uint32_t)(row*40 + k8*8)*2;
            cp16(d, v ? Ah+go : Ah, v);
            cp16(d + OFF_AL*2, v ? Al+go : Al, v);
        }
#pragma unroll
        for (int t = 0; t < B_CH; t++){
            int idx = tid + t*THREADS;
            int row = idx >> 2, k8 = idx & 3;
            int gn = col0 + row, gk = k0 + k8*8;
            bool v = (gn < N) && (gk < K);
            long long go = (long long)gn*ldb + gk;
            uint32_t d = sb + (uint32_t)(OFF_BH + row*40 + k8*8)*2;
            cp16(d, v ? Bh+go : Bh, v);
            cp16(d + 128*40*2, v ? Bl+go : Bl, v);
        }
    };

    int r8 = lane&7, s1 = (lane>>3)&1, s2 = lane>>4;
    auto compute = [&](int st, int kk){
        const __nv_bfloat16* base = sm + st*SH;
        unsigned ah[4][4], al[4][4], bh[2][4], bl[2][4];
#pragma unroll
        for (int mt=0;mt<4;mt++){
            int row = wm0 + mt*16 + r8 + s1*8;
            int col = kk + s2*8;
            ldsm4(ah[mt], base + row*40 + col);
            ldsm4(al[mt], base + OFF_AL + row*40 + col);
        }
#pragma unroll
        for (int np=0;np<2;np++){
            int row = wn0 + np*16 + r8 + s2*8;
            int col = kk + s1*8;
            ldsm4(bh[np], base + OFF_BH + row*40 + col);
            ldsm4(bl[np], base + OFF_BH + 128*40 + row*40 + col);
        }
#pragma unroll
        for (int mt=0;mt<4;mt++)
#pragma unroll
            for (int nt=0;nt<4;nt++){
                unsigned b0h = bh[nt>>1][(nt&1)*2], b1h = bh[nt>>1][(nt&1)*2+1];
                unsigned b0l = bl[nt>>1][(nt&1)*2], b1l = bl[nt>>1][(nt&1)*2+1];
                mma16816(acc[mt][nt], ah[mt], b0h, b1h);
                mma16816(acc[mt][nt], al[mt], b0h, b1h);
                mma16816(acc[mt][nt], ah[mt], b0l, b1l);
            }
    };

    int nk = (K + 31) / 32;
    issue(0); CP_COMMIT();
    if (nk > 1){ issue(1); CP_COMMIT(); }
    for (int kt = 0; kt < nk; kt++){
        if (kt + 1 < nk) { asm volatile("cp.async.wait_group 1;" ::: "memory"); }
        else             { asm volatile("cp.async.wait_group 0;" ::: "memory"); }
        __syncthreads();
        int st = kt % 3;
        compute(st, 0);
        compute(st, 16);
        if (kt + 2 < nk){ issue(kt+2); CP_COMMIT(); }
    }

    // epilogue
    int gid = lane>>2, tq = lane&3;
#pragma unroll
    for (int mt=0;mt<4;mt++)
#pragma unroll
      for (int h=0;h<2;h++){
        int gm = row0 + wm0 + mt*16 + gid + h*8;
        if (gm>=M) continue;
        long long base = (long long)gm*ldc;
#pragma unroll
        for (int nt=0;nt<4;nt++){
          int gn = col0 + wn0 + nt*8 + tq*2;
          if (gn>=N) continue;
          float v0 = alpha*acc[mt][nt][h*2+0];
          float v1 = alpha*acc[mt][nt][h*2+1];
          if (bias){ v0 += bias[gn]; if (gn+1<N) v1 += bias[gn+1]; }
          if (Cr)  { v0 += Cr[base+gn]; if (gn+1<N) v1 += Cr[base+gn+1]; }
          if (gn+1<N){
            float2 st2; st2.x=v0; st2.y=v1; *(float2*)&C[base+gn]=st2;
            if (Ch){
              uint32_t hh, ll; cvt2(v0, v1, hh, ll);
              *(uint32_t*)&Ch[base+gn] = hh;
              *(uint32_t*)&Cl[base+gn] = ll;
            }
          } else {
            C[base+gn]=v0;
            if (Ch){ __nv_bfloat16 hh, ll; cvt1(v0, hh, ll); Ch[base+gn]=hh; Cl[base+gn]=ll; }
          }
        }
      }
}

#define P_NONE  (1<<30), 0LL, 1, 0LL, 0LL
#define P_PLAIN(s) (1<<30), 0LL, 1, (long long)(s), 0LL

static void run_hgemm(const __nv_bfloat16* Ah, const __nv_bfloat16* Al,
                      const __nv_bfloat16* Bh, const __nv_bfloat16* Bl,
                      const float* bias, const float* Cin, float* C,
                      __nv_bfloat16* Ch, __nv_bfloat16* Cl,
                      int M, int N, int K, int lda, int ldb, int ldc,
                      int aD1, long long aS1, int aD2, long long aS2, long long aS3,
                      int bD1, long long bS1, int bD2, long long bS2, long long bS3,
                      long long sCin, long long sC, int batch, float alpha, int addC)
{
    long long b128 = (long long)((N+127)/128)*((M+127)/128)*batch;
    if (M >= 96 && b128 >= 90) {
        constexpr int SM = 3*(2*128+256)*40*2;   // 122880 B
        cudaFuncSetAttribute(hgemm3<128>, cudaFuncAttributeMaxDynamicSharedMemorySize, SM);
        dim3 grid((N+127)/128, (M+127)/128, batch);
        hgemm3<128><<<grid, 256, SM>>>(Ah,Al,Bh,Bl,bias,Cin,C,Ch,Cl,M,N,K,lda,ldb,ldc,
            aD1,aS1,aD2,aS2,aS3,bD1,bS1,bD2,bS2,bS3,sCin,sC,alpha,addC);
    } else {
        constexpr int SM = 3*(2*64+256)*40*2;    // 92160 B
        cudaFuncSetAttribute(hgemm3<64>, cudaFuncAttributeMaxDynamicSharedMemorySize, SM);
        dim3 grid((N+127)/128, (M+63)/64, batch);
        hgemm3<64><<<grid, 128, SM>>>(Ah,Al,Bh,Bl,bias,Cin,C,Ch,Cl,M,N,K,lda,ldb,ldc,
            aD1,aS1,aD2,aS2,aS3,bD1,bS1,bD2,bS2,bS3,sCin,sC,alpha,addC);
    }
}

// ================= transpose-convert: fp32 [K][N] -> bf16 hi/lo [N][Kp] =================
__global__ void tconv(const float* __restrict__ in, __nv_bfloat16* __restrict__ oh,
                      __nv_bfloat16* __restrict__ ol,
                      int K, int N, int Kp, long long sIn, long long sOut)
{
    __shared__ float t[32][33];
    int z = blockIdx.z;
    const float* I = in + (long long)z * sIn;
    __nv_bfloat16* OH = oh + (long long)z * sOut;
    __nv_bfloat16* OL = ol + (long long)z * sOut;
    int kb = blockIdx.y * 32, nb = blockIdx.x * 32;
    for (int i = threadIdx.y; i < 32; i += 8) {
        int k = kb + i, n = nb + threadIdx.x;
        t[i][threadIdx.x] = (k < K && n < N) ? I[(long long)k*N + n] : 0.f;
    }
    __syncthreads();
    for (int i = threadIdx.y; i < 32; i += 8) {
        int n = nb + i, k = kb + threadIdx.x;
        if (n < N && k < Kp) {
            __nv_bfloat16 h, l; cvt1(t[threadIdx.x][i], h, l);
            OH[(long long)n*Kp + k] = h;
            OL[(long long)n*Kp + k] = l;
        }
    }
}

// ---------------- fp32 fallback GEMM (final head, M=8) ----------------
__global__ __launch_bounds__(64)
void sgemm_s(const float* __restrict__ A, const float* __restrict__ B,
             const float* __restrict__ bias, float* __restrict__ C,
             int M, int N, int K, int lda, int ldb, int ldc)
{
    constexpr int BK = 16;
    __shared__ float As[BK][36];
    __shared__ float Bs[BK][36];
    int row0 = blockIdx.y*32, col0 = blockIdx.x*32;
    int tid = threadIdx.x;
    int tx = tid % 8, ty = tid / 8;
    float acc[4][4];
#pragma unroll
    for (int i=0;i<4;i++)
#pragma unroll
      for (int j=0;j<4;j++) acc[i][j]=0.f;
    for (int k0 = 0; k0 < K; k0 += BK) {
        for (int e = tid; e < 32*BK/4; e += 64) {
            int mm = e >> 2, c4 = e & 3;
            int gm = row0+mm, gk = k0+c4*4;
            float4 v = make_float4(0.f,0.f,0.f,0.f);
            if (gm < M && gk < K) v = *(const float4*)&A[(long long)gm*lda+gk];
            As[c4*4+0][mm]=v.x; As[c4*4+1][mm]=v.y; As[c4*4+2][mm]=v.z; As[c4*4+3][mm]=v.w;
        }
        for (int e = tid; e < BK*8; e += 64) {
            int kk = e / 8, n4 = e % 8;
            int gk = k0+kk, gn = col0+n4*4;
            float4 v = make_float4(0.f,0.f,0.f,0.f);
            if (gk < K) {
                if (gn+3 < N) v = *(const float4*)&B[(long long)gk*ldb+gn];
                else {
                    const float* p = &B[(long long)gk*ldb];
                    if (gn<N)v.x=p[gn]; if (gn+1<N)v.y=p[gn+1];
                    if (gn+2<N)v.z=p[gn+2]; if (gn+3<N)v.w=p[gn+3];
                }
            }
            Bs[kk][n4*4+0]=v.x; Bs[kk][n4*4+1]=v.y; Bs[kk][n4*4+2]=v.z; Bs[kk][n4*4+3]=v.w;
        }
        __syncthreads();
#pragma unroll
        for (int kk = 0; kk < BK; kk++) {
            float a[4], b[4];
#pragma unroll
            for (int i=0;i<4;i++) a[i]=As[kk][ty*4+i];
#pragma unroll
            for (int j=0;j<4;j++) b[j]=Bs[kk][tx*4+j];
#pragma unroll
            for (int i=0;i<4;i++)
#pragma unroll
              for (int j=0;j<4;j++) acc[i][j]+=a[i]*b[j];
        }
        __syncthreads();
    }
#pragma unroll
    for (int i=0;i<4;i++){
        int gm = row0+ty*4+i;
        if (gm >= M) continue;
#pragma unroll
        for (int j=0;j<4;j++){
            int gn = col0+tx*4+j;
            if (gn >= N) continue;
            float v = acc[i][j];
            if (bias) v += bias[gn];
            C[(long long)gm*ldc+gn] = v;
        }
    }
}

// ---------------- elementwise kernels ----------------
__global__ void patch_gather2(const float* __restrict__ img,
                              __nv_bfloat16* __restrict__ oh, __nv_bfloat16* __restrict__ ol) {
    int idx = blockIdx.x*blockDim.x + threadIdx.x;
    int total = BATCH*NPATCH*PK;
    if (idx >= total) return;
    int k = idx % PK;
    int p = (idx / PK) % NPATCH;
    int b = idx / (PK*NPATCH);
    int c  = k % 3;
    int pj = (k/3) % 16;
    int pi = k / 48;
    int i = p / 14, j = p % 14;
    float v = img[(((long long)b*3 + c)*224 + (i*16+pi))*224 + (j*16+pj)];
    __nv_bfloat16 h, l; cvt1(v, h, l);
    oh[idx] = h; ol[idx] = l;
}

__global__ void assemble_x_kernel(const float* __restrict__ xp, const float* __restrict__ cls,
                                  float* __restrict__ x) {
    int idx = blockIdx.x*blockDim.x + threadIdx.x;
    int total = BATCH*SEQ*DIM;
    if (idx >= total) return;
    int d = idx % DIM;
    int m = (idx / DIM) % SEQ;
    int b = idx / (DIM*SEQ);
    x[idx] = (m == 0) ? cls[d] : xp[((long long)b*NPATCH + (m-1))*DIM + d];
}

__global__ void rms_part_kernel(const float* __restrict__ x, float* __restrict__ red) {
    int b = blockIdx.y, ch = blockIdx.x;
    const int per_batch = SEQ*DIM;
    const int chunk = per_batch/32;
    const float4* p = (const float4*)(x + (long long)b*per_batch + ch*chunk);
    float s = 0.f;
    for (int i = threadIdx.x; i < chunk/4; i += 256) {
        float4 v = p[i];
        s += v.x*v.x + v.y*v.y + v.z*v.z + v.w*v.w;
    }
    __shared__ float sm[256];
    sm[threadIdx.x] = s; __syncthreads();
    for (int o = 128; o > 0; o >>= 1) { if (threadIdx.x < o) sm[threadIdx.x] += sm[threadIdx.x+o]; __syncthreads(); }
    if (threadIdx.x == 0) red[b*32 + ch] = sm[0];
}
__global__ void rms_fin_kernel(const float* __restrict__ red, float* __restrict__ fac) {
    int b = threadIdx.x / 32, lane = threadIdx.x % 32;
    float v = red[b*32 + lane];
    for (int o = 16; o; o >>= 1) v += __shfl_xor_sync(0xffffffffu, v, o);
    if (lane == 0) fac[b] = sqrtf((float)(SEQ*DIM) / v);
}
__global__ void rms_apply2(float* __restrict__ x, const float* __restrict__ fac,
                           const float* __restrict__ scale,
                           uint2* __restrict__ xh, uint2* __restrict__ xl) {
    int idx = blockIdx.x*blockDim.x + threadIdx.x;
    const int per4 = SEQ*DIM/4;
    int total = BATCH*per4;
    if (idx >= total) return;
    int b = idx / per4, s4 = idx % per4;
    float f = fac[b];
    float4 v = ((float4*)x)[idx];
    float4 sc = ((const float4*)scale)[s4];
    v.x *= f*sc.x; v.y *= f*sc.y; v.z *= f*sc.z; v.w *= f*sc.w;
    ((float4*)x)[idx] = v;
    uint2 h, l; cvt4(v, h, l);
    xh[idx] = h; xl[idx] = l;
}

// rope table: identical per-element float ops as before (bit-identical values)
__global__ void rope_tab(float2* __restrict__ tab, int M, int half, float cc) {
    int idx = blockIdx.x*blockDim.x + threadIdx.x;
    if (idx >= M*half) return;
    int i = idx % half, m = idx / half;
    float theta = exp2f(cc * ((float)i - 1.f));
    float ang = (float)m * theta;
    float s, c;
    sincosf(ang, &s, &c);
    tab[idx] = make_float2(c, s);
}

__global__ void rope3(const float* __restrict__ q, const float* __restrict__ k,
                      __nv_bfloat16* __restrict__ qh, __nv_bfloat16* __restrict__ ql,
                      __nv_bfloat16* __restrict__ kh, __nv_bfloat16* __restrict__ kl,
                      const float2* __restrict__ tab, int Z, int M, int D) {
    int half = D / 2;
    long long total = (long long)Z * M * half;
    long long idx = (long long)blockIdx.x*blockDim.x + threadIdx.x;
    if (idx >= total) return;
    int i = (int)(idx % half);
    int m = (int)((idx / half) % M);
    long long z = idx / ((long long)half * M);
    float2 cs = tab[m*half + i];
    float c = cs.x, s = cs.y;
    long long base = ((z*M) + m) * (long long)D + 2*i;
    float xe, xo, re, ro;
    uint32_t h, l;
    xe = q[base]; xo = q[base+1];
    re = xe*c + xo*s; ro = -xe*s + xo*c;
    cvt2(re, ro, h, l);
    *(uint32_t*)&qh[base] = h; *(uint32_t*)&ql[base] = l;
    xe = k[base]; xo = k[base+1];
    re = xe*c + xo*s; ro = -xe*s + xo*c;
    cvt2(re, ro, h, l);
    *(uint32_t*)&kh[base] = h; *(uint32_t*)&kl[base] = l;
}

__global__ void softmax2(float* __restrict__ s,
                         __nv_bfloat16* __restrict__ ph, __nv_bfloat16* __restrict__ pl,
                         int rows, int L, int ld) {
    int warp = (blockIdx.x*blockDim.x + threadIdx.x) / 32;
    int lane = threadIdx.x % 32;
    if (warp >= rows) return;
    long long ro = (long long)warp * ld;
    float* row = s + ro;
    float mx = -1e30f;
    for (int i = lane; i < L; i += 32) mx = fmaxf(mx, row[i]);
    for (int o = 16; o; o >>= 1) mx = fmaxf(mx, __shfl_xor_sync(0xffffffffu, mx, o));
    float sum = 0.f;
    for (int i = lane; i < L; i += 32) { float e = __expf(row[i]-mx); row[i] = e; sum += e; }
    for (int o = 16; o; o >>= 1) sum += __shfl_xor_sync(0xffffffffu, sum, o);
    float inv = 1.f / sum;
    for (int i = lane; i < ld; i += 32) {
        float v = (i < L) ? row[i]*inv : 0.f;
        __nv_bfloat16 h, l; cvt1(v, h, l);
        ph[ro + i] = h; pl[ro + i] = l;
    }
}

// x[b][m][:] += bias + sum_h part[(h*8+b)][m][:]   ([h][b] slice order)
__global__ void attn_reduce_kernel(const float* __restrict__ part,
                                   const float* __restrict__ bias,
                                   float* __restrict__ x) {
    int idx = blockIdx.x*blockDim.x + threadIdx.x;
    const int D4 = DIM/4;
    int total = BATCH*SEQ*D4;
    if (idx >= total) return;
    int d4 = idx % D4;
    int m  = (idx / D4) % SEQ;
    int b  = idx / (D4*SEQ);
    float4 acc = ((float4*)x)[idx];
    float4 bb = ((const float4*)bias)[d4];
    acc.x += bb.x; acc.y += bb.y; acc.z += bb.z; acc.w += bb.w;
#pragma unroll
    for (int h = 0; h < HEADS; h++) {
        float4 p = ((const float4*)part)[((long long)(h*BATCH+b)*SEQ + m)*D4 + d4];
        acc.x += p.x; acc.y += p.y; acc.z += p.z; acc.w += p.w;
    }
    ((float4*)x)[idx] = acc;
}

__global__ void x_to_y2(const float* __restrict__ x, float* __restrict__ y,
                        __nv_bfloat16* __restrict__ yh, __nv_bfloat16* __restrict__ yl) {
    int idx = blockIdx.x*blockDim.x + threadIdx.x;
    int total = BATCH*CDIM*TDIM;
    if (idx >= total) return;
    int t = idx % TDIM;
    int c = (idx / TDIM) % CDIM;
    int b = idx / (TDIM*CDIM);
    int f = t / SEQ, mm = t % SEQ;
    float v = x[((long long)b*SEQ + mm)*DIM + c*8 + f];
    y[idx] = v;
    __nv_bfloat16 h, l; cvt1(v, h, l);
    yh[idx] = h; yl[idx] = l;
}

__global__ void y_to_x_kernel(const float* __restrict__ y, float* __restrict__ x) {
    int idx = blockIdx.x*blockDim.x + threadIdx.x;
    int total = BATCH*SEQ*DIM;
    if (idx >= total) return;
    int d  = idx % DIM;
    int mm = (idx / DIM) % SEQ;
    int b  = idx / (DIM*SEQ);
    int c = d >> 3, f = d & 7;
    x[idx] = y[((long long)b*CDIM + c)*TDIM + f*SEQ + mm];
}

__global__ void cls_ln_kernel(const float* __restrict__ x, const float* __restrict__ g,
                              const float* __restrict__ be, float* __restrict__ out) {
    int b = blockIdx.x, t = threadIdx.x;
    const float* row = x + (long long)b*SEQ*DIM;
    __shared__ float red[256];
    float s = 0.f;
    for (int i = t; i < DIM; i += 256) s += row[i];
    red[t] = s; __syncthreads();
    for (int o = 128; o > 0; o >>= 1) { if (t < o) red[t] += red[t+o]; __syncthreads(); }
    float mu = red[0] / DIM; __syncthreads();
    float v = 0.f;
    for (int i = t; i < DIM; i += 256) { float d = row[i]-mu; v += d*d; }
    red[t] = v; __syncthreads();
    for (int o = 128; o > 0; o >>= 1) { if (t < o) red[t] += red[t+o]; __syncthreads(); }
    float inv = rsqrtf(red[0]/DIM + 1e-5f);
    for (int i = t; i < DIM; i += 256) out[b*DIM + i] = (row[i]-mu)*inv*g[i] + be[i];
}

static inline int nblk(long long n, int t) { return (int)((n + t - 1) / t); }

extern "C" void kernel_launch(void* const* d_in, const int* in_sizes, int n_in,
                              void* d_out, int out_size) {
    const float* img       = (const float*)d_in[0];
    const float* patch_W   = (const float*)d_in[1];
    const float* patch_b   = (const float*)d_in[2];
    const float* cls_token = (const float*)d_in[3];
    const float* rms_scale = (const float*)d_in[4];
    const float* Wq        = (const float*)d_in[5];
    const float* Wk        = (const float*)d_in[6];
    const float* Wv        = (const float*)d_in[7];
    const float* attn_W    = (const float*)d_in[8];
    const float* attn_b    = (const float*)d_in[9];
    const float* tWq       = (const float*)d_in[10];
    const float* tWk       = (const float*)d_in[11];
    const float* tWv       = (const float*)d_in[12];
    const float* ln_g      = (const float*)d_in[13];
    const float* ln_b      = (const float*)d_in[14];
    const float* head_W    = (const float*)d_in[15];
    const float* head_b    = (const float*)d_in[16];
    float* out = (float*)d_out;

    float *pxp,*px,*pqkv,*ps,*po,*pot,*py,*ptqkv,*pts,*pf,*pred,*pcls;
    float2 *ptab1,*ptab2;
    cudaGetSymbolAddress((void**)&pxp,  g_xp);
    cudaGetSymbolAddress((void**)&px,   g_x);
    cudaGetSymbolAddress((void**)&pqkv, g_qkv);
    cudaGetSymbolAddress((void**)&ps,   g_sc);
    cudaGetSymbolAddress((void**)&po,   g_o);
    cudaGetSymbolAddress((void**)&pot,  g_ot);
    cudaGetSymbolAddress((void**)&py,   g_y);
    cudaGetSymbolAddress((void**)&ptqkv,g_tqkv);
    cudaGetSymbolAddress((void**)&pts,  g_ts);
    cudaGetSymbolAddress((void**)&pf,   g_fac);
    cudaGetSymbolAddress((void**)&pred, g_red);
    cudaGetSymbolAddress((void**)&pcls, g_cls);
    cudaGetSymbolAddress((void**)&ptab1, g_tab1);
    cudaGetSymbolAddress((void**)&ptab2, g_tab2);

    __nv_bfloat16 *path_h,*path_l,*xh,*xl,*qh,*ql,*kh,*kl,*ph,*pl,*oh,*ol;
    __nv_bfloat16 *yh,*yl,*tqh,*tql,*tkh,*tkl,*tsh,*tsl;
    __nv_bfloat16 *pwh,*pwl,*wAh,*wAl,*awh,*awl,*twAh,*twAl,*vth,*vtl,*tvth,*tvtl;
    cudaGetSymbolAddress((void**)&path_h, g_path_h); cudaGetSymbolAddress((void**)&path_l, g_path_l);
    cudaGetSymbolAddress((void**)&xh,  g_xh);  cudaGetSymbolAddress((void**)&xl,  g_xl);
    cudaGetSymbolAddress((void**)&qh,  g_qh);  cudaGetSymbolAddress((void**)&ql,  g_ql);
    cudaGetSymbolAddress((void**)&kh,  g_kh);  cudaGetSymbolAddress((void**)&kl,  g_kl);
    cudaGetSymbolAddress((void**)&ph,  g_ph);  cudaGetSymbolAddress((void**)&pl,  g_pl);
    cudaGetSymbolAddress((void**)&oh,  g_oh);  cudaGetSymbolAddress((void**)&ol,  g_ol);
    cudaGetSymbolAddress((void**)&yh,  g_yh);  cudaGetSymbolAddress((void**)&yl,  g_yl);
    cudaGetSymbolAddress((void**)&tqh, g_tqh); cudaGetSymbolAddress((void**)&tql, g_tql);
    cudaGetSymbolAddress((void**)&tkh, g_tkh); cudaGetSymbolAddress((void**)&tkl, g_tkl);
    cudaGetSymbolAddress((void**)&tsh, g_tsh); cudaGetSymbolAddress((void**)&tsl, g_tsl);
    cudaGetSymbolAddress((void**)&pwh,  g_pwh);  cudaGetSymbolAddress((void**)&pwl,  g_pwl);
    cudaGetSymbolAddress((void**)&wAh,  g_wAh);  cudaGetSymbolAddress((void**)&wAl,  g_wAl);
    cudaGetSymbolAddress((void**)&awh,  g_awh);  cudaGetSymbolAddress((void**)&awl,  g_awl);
    cudaGetSymbolAddress((void**)&twAh, g_twAh); cudaGetSymbolAddress((void**)&twAl, g_twAl);
    cudaGetSymbolAddress((void**)&vth,  g_vth);  cudaGetSymbolAddress((void**)&vtl,  g_vtl);
    cudaGetSymbolAddress((void**)&tvth, g_tvth); cudaGetSymbolAddress((void**)&tvtl, g_tvtl);

    const long long sQH  = (long long)SEQ*DIM;
    const long long sSSp = (long long)SEQ*SEQP;
    const long long sY   = (long long)CDIM*TDIM;
    const long long sTS  = (long long)CDIM*CDIM;
    const long long sW   = (long long)DIM*DIM;
    const long long sVT  = (long long)DIM*SEQP;
    const long long sTVT = (long long)TDIM*CDIM;
    const long long sTW  = (long long)TDIM*TDIM;
    const float scale1 = (float)(1.0/sqrt(512.0));
    const float scale2 = (float)(1.0/sqrt(1576.0));
    const float cc1 = (float)(-2.0*log2(10000.0)/512.0);
    const float cc2 = (float)(-2.0*log2(10000.0)/1576.0);
    dim3 tcb(32, 8);

    // ---- rope tables (layer-independent) ----
    rope_tab<<<nblk(SEQ*256,256),256>>>(ptab1, SEQ, 256, cc1);
    rope_tab<<<nblk(CDIM*788,256),256>>>(ptab2, CDIM, 788, cc2);

    // ---- weight pre-conversion into combined buffers ----
    tconv<<<dim3(DIM/32, PK/32, 1), tcb>>>(patch_W, pwh, pwl, PK, DIM, PK, 0, 0);
    for (int l = 0; l < 2; l++) {
        const float* srcs[3] = {Wq, Wk, Wv};
        for (int w = 0; w < 3; w++) {
            tconv<<<dim3(16, 16, 8), tcb>>>(srcs[w] + (long long)l*8*sW,
                                            wAh + ((long long)l*24 + w*8)*sW,
                                            wAl + ((long long)l*24 + w*8)*sW,
                                            DIM, DIM, DIM, sW, sW);
        }
        const float* tsrcs[3] = {tWq, tWk, tWv};
        for (int w = 0; w < 3; w++) {
            tconv<<<dim3(50, 50, 1), tcb>>>(tsrcs[w] + (long long)l*sTW,
                                            twAh + ((long long)l*3 + w)*sTW,
                                            twAl + ((long long)l*3 + w)*sTW,
                                            TDIM, TDIM, TDIM, 0, 0);
        }
    }
    tconv<<<dim3(16, 16, 16), tcb>>>(attn_W, awh, awl, DIM, DIM, DIM, sW, sW);

    // ---- patch embedding ----
    patch_gather2<<<nblk((long long)BATCH*NPATCH*PK,256),256>>>(img, path_h, path_l);
    run_hgemm(path_h, path_l, pwh, pwl, patch_b, 0, pxp, 0, 0,
              BATCH*NPATCH, DIM, PK, PK, PK, DIM,
              P_NONE, P_NONE, 0, 0, 1, 1.f, 0);
    assemble_x_kernel<<<nblk((long long)BATCH*SEQ*DIM,256),256>>>(pxp, cls_token, px);

    for (int l = 0; l < 2; l++) {
        const float* scale_l = rms_scale + (long long)l*SEQ*DIM;

        // rmsnorm #1 (+split)
        rms_part_kernel<<<dim3(32,BATCH),256>>>(px, pred);
        rms_fin_kernel<<<1,256>>>(pred, pf);
        rms_apply2<<<nblk((long long)BATCH*SEQ*DIM/4,256),256>>>(px, pf, scale_l,
                                                                 (uint2*)xh, (uint2*)xl);

        // fused QKV, batch folded into M: M=1576, z = w*8+h (24 batches)
        run_hgemm(xh, xl, wAh + (long long)l*24*sW, wAl + (long long)l*24*sW, 0, 0, pqkv, 0, 0,
                  BATCH*SEQ, DIM, DIM, DIM, DIM, DIM,
                  P_NONE,
                  8, 8*sW, 8, 0LL, sW,
                  0, 8*sQH, 24, 1.f, 0);

        // v -> vT split [DIM][SEQP]
        tconv<<<dim3(16, 7, 64), tcb>>>(pqkv + 128*sQH, vth, vtl, SEQ, DIM, SEQP, sQH, sVT);

        // RoPE -> split q,k (table-driven)
        rope3<<<nblk((long long)64*SEQ*(DIM/2),256),256>>>(pqkv, pqkv + 64*sQH,
                                                           qh, ql, kh, kl, ptab1, 64, SEQ, DIM);

        // scores
        run_hgemm(qh, ql, kh, kl, 0, 0, ps, 0, 0,
                  SEQ, SEQ, DIM, DIM, DIM, SEQP,
                  P_PLAIN(sQH), P_PLAIN(sQH), 0, sSSp, 64, scale1, 0);
        softmax2<<<nblk((long long)64*SEQ*32,256),256>>>(ps, ph, pl, 64*SEQ, SEQ, SEQP);

        // o = p @ v (epilogue emits split oh/ol)
        run_hgemm(ph, pl, vth, vtl, 0, 0, po, oh, ol,
                  SEQ, DIM, SEQP, SEQP, SEQP, DIM,
                  P_PLAIN(sSSp), P_PLAIN(sVT), 0, sQH, 64, 1.f, 0);

        // proj partials, batch folded into M: M=1576, z=h (8 batches)
        run_hgemm(oh, ol, awh + (long long)l*8*sW, awl + (long long)l*8*sW, 0, 0, pot, 0, 0,
                  BATCH*SEQ, DIM, DIM, DIM, DIM, DIM,
                  P_PLAIN(8*sQH), P_PLAIN(sW), 0, 8*sQH, 8, 1.f, 0);
        attn_reduce_kernel<<<nblk((long long)BATCH*SEQ*DIM/4,256),256>>>(pot, attn_b + l*DIM, px);

        // rmsnorm #2 (+split)
        rms_part_kernel<<<dim3(32,BATCH),256>>>(px, pred);
        rms_fin_kernel<<<1,256>>>(pred, pf);
        rms_apply2<<<nblk((long long)BATCH*SEQ*DIM/4,256),256>>>(px, pf, scale_l,
                                                                 (uint2*)xh, (uint2*)xl);

        // token-mixing
        x_to_y2<<<nblk((long long)BATCH*CDIM*TDIM,256),256>>>(px, py, yh, yl);

        // fused token QKV, batch folded into M: M=512, z=w (3 batches)
        run_hgemm(yh, yl, twAh + (long long)l*3*sTW, twAl + (long long)l*3*sTW, 0, 0, ptqkv, 0, 0,
                  BATCH*CDIM, TDIM, TDIM, TDIM, TDIM, TDIM,
                  P_NONE, P_PLAIN(sTW), 0, 8*sY, 3, 1.f, 0);

        // tv -> tvT split
        tconv<<<dim3(50, 2, 8), tcb>>>(ptqkv + 16*sY, tvth, tvtl, CDIM, TDIM, CDIM, sY, sTVT);

        // RoPE -> split tq,tk (table-driven)
        rope3<<<nblk((long long)BATCH*CDIM*(TDIM/2),256),256>>>(ptqkv, ptqkv + 8*sY,
                                                                 tqh, tql, tkh, tkl,
                                                                 ptab2, BATCH, CDIM, TDIM);

        // token scores
        run_hgemm(tqh, tql, tkh, tkl, 0, 0, pts, 0, 0,
                  CDIM, CDIM, TDIM, TDIM, TDIM, CDIM,
                  P_PLAIN(sY), P_PLAIN(sY), 0, sTS, BATCH, scale2, 0);
        softmax2<<<nblk((long long)BATCH*CDIM*32,256),256>>>(pts, tsh, tsl,
                                                             BATCH*CDIM, CDIM, CDIM);

        // y += p @ tv
        run_hgemm(tsh, tsl, tvth, tvtl, 0, py, py, 0, 0,
                  CDIM, TDIM, CDIM, CDIM, CDIM, TDIM,
                  P_PLAIN(sTS), P_PLAIN(sTVT), sY, sY, BATCH, 1.f, 1);

        y_to_x_kernel<<<nblk((long long)BATCH*SEQ*DIM,256),256>>>(py, px);
    }

    // ---- final: cls layernorm + head ----
    cls_ln_kernel<<<BATCH,256>>>(px, ln_g, ln_b, pcls);
    {
        dim3 grid((NCLS+31)/32, 1, 1);
        sgemm_s<<<grid, 64>>>(pcls, head_W, head_b, out, BATCH, NCLS, DIM, DIM, NCLS, NCLS);
    }
}

// round 15
// speedup vs baseline: 1.6440x; 1.0493x over previous
#include <cuda_runtime.h>
#include <cuda_bf16.h>
#include <math.h>
#include <stdint.h>

#define BATCH 8
#define HEADS 8
#define DIM 512
#define SEQ 197
#define SEQP 208
#define NPATCH 196
#define PK 768
#define CDIM 64
#define TDIM 1576
#define TDIMP 1600
#define NCLS 1000

// ---------------- fp32 scratch ----------------
__device__ float g_xp[BATCH*NPATCH*DIM];
__device__ float g_x[BATCH*SEQ*DIM];
__device__ float g_qkv[192*SEQ*DIM];          // [w][h][b][SEQ][DIM]
__device__ float g_sc[BATCH*HEADS*SEQ*SEQP];
__device__ float g_o[BATCH*HEADS*SEQ*DIM];
__device__ float g_ot[BATCH*SEQ*HEADS*DIM];   // proj partials [h][b][SEQ][DIM]
__device__ float g_y[BATCH*CDIM*TDIM];
__device__ float g_tqkv[24*CDIM*TDIM];        // [w][b][CDIM][TDIM]
__device__ float g_ts[BATCH*CDIM*CDIM];
__device__ float g_ts4[32*CDIM*CDIM];         // split-K partials [b][c][64][64]
__device__ float g_fac[BATCH];
__device__ float g_red[BATCH*32];
__device__ float g_cls[BATCH*DIM];
__device__ float2 g_tab1[SEQ*256];            // attention rope table [m][i]
__device__ float2 g_tab2[CDIM*788];           // token rope table [m][i]

// ---------------- bf16 hi/lo split operands (K-major) ----------------
__device__ __nv_bfloat16 g_path_h[BATCH*NPATCH*PK],  g_path_l[BATCH*NPATCH*PK];
__device__ __nv_bfloat16 g_xh[BATCH*SEQ*DIM],        g_xl[BATCH*SEQ*DIM];
__device__ __nv_bfloat16 g_qh[BATCH*HEADS*SEQ*DIM],  g_ql[BATCH*HEADS*SEQ*DIM];
__device__ __nv_bfloat16 g_kh[BATCH*HEADS*SEQ*DIM],  g_kl[BATCH*HEADS*SEQ*DIM];
__device__ __nv_bfloat16 g_ph[BATCH*HEADS*SEQ*SEQP], g_pl[BATCH*HEADS*SEQ*SEQP];
__device__ __nv_bfloat16 g_oh[BATCH*HEADS*SEQ*DIM],  g_ol[BATCH*HEADS*SEQ*DIM];
__device__ __nv_bfloat16 g_yh[BATCH*CDIM*TDIM],      g_yl[BATCH*CDIM*TDIM];
__device__ __nv_bfloat16 g_tqh[BATCH*CDIM*TDIMP],    g_tql[BATCH*CDIM*TDIMP];   // padded; pad stays zero
__device__ __nv_bfloat16 g_tkh[BATCH*CDIM*TDIMP],    g_tkl[BATCH*CDIM*TDIMP];
__device__ __nv_bfloat16 g_tsh[BATCH*CDIM*CDIM],     g_tsl[BATCH*CDIM*CDIM];
// weights
__device__ __nv_bfloat16 g_pwh[DIM*PK],            g_pwl[DIM*PK];
__device__ __nv_bfloat16 g_wAh[2*3*8*DIM*DIM],     g_wAl[2*3*8*DIM*DIM];   // [l][w][h]
__device__ __nv_bfloat16 g_awh[16*DIM*DIM],        g_awl[16*DIM*DIM];
__device__ __nv_bfloat16 g_twAh[2*3*TDIM*TDIM],    g_twAl[2*3*TDIM*TDIM]; // [l][w]
__device__ __nv_bfloat16 g_vth[64*DIM*SEQP],       g_vtl[64*DIM*SEQP];
__device__ __nv_bfloat16 g_tvth[8*TDIM*CDIM],      g_tvtl[8*TDIM*CDIM];

// ---------------- helpers ----------------
__device__ __forceinline__ void cvt4(float4 v, uint2 &h, uint2 &l){
    __nv_bfloat16 ax=__float2bfloat16_rn(v.x), ay=__float2bfloat16_rn(v.y);
    __nv_bfloat16 az=__float2bfloat16_rn(v.z), aw=__float2bfloat16_rn(v.w);
    __nv_bfloat162 h0; h0.x=ax; h0.y=ay;
    __nv_bfloat162 h1; h1.x=az; h1.y=aw;
    h.x=*(unsigned*)&h0; h.y=*(unsigned*)&h1;
    __nv_bfloat162 l0; l0.x=__float2bfloat16_rn(v.x-__bfloat162float(ax));
                       l0.y=__float2bfloat16_rn(v.y-__bfloat162float(ay));
    __nv_bfloat162 l1; l1.x=__float2bfloat16_rn(v.z-__bfloat162float(az));
                       l1.y=__float2bfloat16_rn(v.w-__bfloat162float(aw));
    l.x=*(unsigned*)&l0; l.y=*(unsigned*)&l1;
}
__device__ __forceinline__ void cvt2(float a, float b, uint32_t &h, uint32_t &l){
    __nv_bfloat16 ha=__float2bfloat16_rn(a), hb=__float2bfloat16_rn(b);
    __nv_bfloat162 H; H.x=ha; H.y=hb; h=*(uint32_t*)&H;
    __nv_bfloat162 L; L.x=__float2bfloat16_rn(a-__bfloat162float(ha));
                      L.y=__float2bfloat16_rn(b-__bfloat162float(hb)); l=*(uint32_t*)&L;
}
__device__ __forceinline__ void cvt1(float a, __nv_bfloat16 &h, __nv_bfloat16 &l){
    h=__float2bfloat16_rn(a);
    l=__float2bfloat16_rn(a-__bfloat162float(h));
}
__device__ __forceinline__ void ldsm4(unsigned r[4], const __nv_bfloat16* p) {
    unsigned a = (unsigned)__cvta_generic_to_shared(p);
    asm volatile("ldmatrix.sync.aligned.m8n8.x4.shared.b16 {%0,%1,%2,%3}, [%4];"
                 : "=r"(r[0]), "=r"(r[1]), "=r"(r[2]), "=r"(r[3]) : "r"(a));
}
__device__ __forceinline__ void mma16816(float c[4], const unsigned a[4],
                                         unsigned b0, unsigned b1) {
    asm volatile("mma.sync.aligned.m16n8k16.row.col.f32.bf16.bf16.f32 "
                 "{%0,%1,%2,%3}, {%4,%5,%6,%7}, {%8,%9}, {%0,%1,%2,%3};"
                 : "+f"(c[0]), "+f"(c[1]), "+f"(c[2]), "+f"(c[3])
                 : "r"(a[0]), "r"(a[1]), "r"(a[2]), "r"(a[3]), "r"(b0), "r"(b1));
}
__device__ __forceinline__ void cp16(uint32_t dst, const void* src, bool valid){
    uint64_t g;
    asm("cvta.to.global.u64 %0, %1;" : "=l"(g) : "l"(src));
    int sz = valid ? 16 : 0;
    asm volatile("cp.async.cg.shared.global [%0], [%1], 16, %2;"
                 :: "r"(dst), "l"(g), "r"(sz) : "memory");
}
#define CP_COMMIT() asm volatile("cp.async.commit_group;" ::: "memory")

// ================= bf16 split GEMM: cp.async 3-stage pipeline (R12-proven) ==================
// off(z) = (z/D1)*S1 + ((z%D1)/D2)*S2 + (z%D2)*S3  for A and B independently.
template<int BM>
__global__ __launch_bounds__(BM*2)
void hgemm3(const __nv_bfloat16* __restrict__ Ah, const __nv_bfloat16* __restrict__ Al,
            const __nv_bfloat16* __restrict__ Bh, const __nv_bfloat16* __restrict__ Bl,
            const float* __restrict__ bias, const float* __restrict__ Cin,
            float* __restrict__ C,
            __nv_bfloat16* __restrict__ Ch, __nv_bfloat16* __restrict__ Cl,
            int M, int N, int K, int lda, int ldb, int ldc,
            int aD1, long long aS1, int aD2, long long aS2, long long aS3,
            int bD1, long long bS1, int bD2, long long bS2, long long bS3,
            long long sCin, long long sC, float alpha, int addC)
{
    constexpr int WARPS_M = BM/64;
    constexpr int THREADS = BM*2;
    constexpr int A_CH = BM*4/THREADS;
    constexpr int B_CH = 512/THREADS;
    constexpr int SH = (2*BM + 256)*40;      // halves per stage
    const int OFF_AL = BM*40, OFF_BH = 2*BM*40;
    extern __shared__ __align__(16) __nv_bfloat16 sm[];
    uint32_t smem_base = (uint32_t)__cvta_generic_to_shared(sm);

    int z = blockIdx.z;
    long long ao = (long long)(z / aD1)*aS1 + (long long)((z % aD1) / aD2)*aS2
                 + (long long)(z % aD2)*aS3;
    long long bo = (long long)(z / bD1)*bS1 + (long long)((z % bD1) / bD2)*bS2
                 + (long long)(z % bD2)*bS3;
    Ah += ao; Al += ao; Bh += bo; Bl += bo;
    long long co = (long long)z * sC;
    C += co;
    if (Ch){ Ch += co; Cl += co; }
    const float* Cr = addC ? Cin + (long long)z * sCin : (const float*)0;

    int row0 = blockIdx.y*BM, col0 = blockIdx.x*128;
    int tid = threadIdx.x, lane = tid & 31, warp = tid >> 5;
    int wm0 = (warp % WARPS_M)*64;
    int wn0 = (warp / WARPS_M)*32;

    float acc[4][4][4];
#pragma unroll
    for (int i=0;i<4;i++)
#pragma unroll
      for (int j=0;j<4;j++)
#pragma unroll
        for (int t=0;t<4;t++) acc[i][j][t]=0.f;

    auto issue = [&](int kt){
        int st = kt % 3;
        uint32_t sb = smem_base + st*SH*2;
        int k0 = kt*32;
#pragma unroll
        for (int t = 0; t < A_CH; t++){
            int idx = tid + t*THREADS;
            int row = idx >> 2, k8 = idx & 3;
            int gm = row0 + row, gk = k0 + k8*8;
            bool v = (gm < M) && (gk < K);
            long long go = (long long)gm*lda + gk;
            uint32_t d = sb + (uint32_t)(row*40 + k8*8)*2;
            cp16(d, v ? Ah+go : Ah, v);
            cp16(d + OFF_AL*2, v ? Al+go : Al, v);
        }
#pragma unroll
        for (int t = 0; t < B_CH; t++){
            int idx = tid + t*THREADS;
            int row = idx >> 2, k8 = idx & 3;
            int gn = col0 + row, gk = k0 + k8*8;
            bool v = (gn < N) && (gk < K);
            long long go = (long long)gn*ldb + gk;
            uint32_t d = sb + (uint32_t)(OFF_BH + row*40 + k8*8)*2;
            cp16(d, v ? Bh+go : Bh, v);
            cp16(d + 128*40*2, v ? Bl+go : Bl, v);
        }
    };

    int r8 = lane&7, s1 = (lane>>3)&1, s2 = lane>>4;
    auto compute = [&](int st, int kk){
        const __nv_bfloat16* base = sm + st*SH;
        unsigned ah[4][4], al[4][4], bh[2][4], bl[2][4];
#pragma unroll
        for (int mt=0;mt<4;mt++){
            int row = wm0 + mt*16 + r8 + s1*8;
            int col = kk + s2*8;
            ldsm4(ah[mt], base + row*40 + col);
            ldsm4(al[mt], base + OFF_AL + row*40 + col);
        }
#pragma unroll
        for (int np=0;np<2;np++){
            int row = wn0 + np*16 + r8 + s2*8;
            int col = kk + s1*8;
            ldsm4(bh[np], base + OFF_BH + row*40 + col);
            ldsm4(bl[np], base + OFF_BH + 128*40 + row*40 + col);
        }
#pragma unroll
        for (int mt=0;mt<4;mt++)
#pragma unroll
            for (int nt=0;nt<4;nt++){
                unsigned b0h = bh[nt>>1][(nt&1)*2], b1h = bh[nt>>1][(nt&1)*2+1];
                unsigned b0l = bl[nt>>1][(nt&1)*2], b1l = bl[nt>>1][(nt&1)*2+1];
                mma16816(acc[mt][nt], ah[mt], b0h, b1h);
                mma16816(acc[mt][nt], al[mt], b0h, b1h);
                mma16816(acc[mt][nt], ah[mt], b0l, b1l);
            }
    };

    int nk = (K + 31) / 32;
    issue(0); CP_COMMIT();
    if (nk > 1){ issue(1); CP_COMMIT(); }
    for (int kt = 0; kt < nk; kt++){
        if (kt + 1 < nk) { asm volatile("cp.async.wait_group 1;" ::: "memory"); }
        else             { asm volatile("cp.async.wait_group 0;" ::: "memory"); }
        __syncthreads();
        int st = kt % 3;
        compute(st, 0);
        compute(st, 16);
        if (kt + 2 < nk){ issue(kt+2); CP_COMMIT(); }
    }

    // epilogue
    int gid = lane>>2, tq = lane&3;
#pragma unroll
    for (int mt=0;mt<4;mt++)
#pragma unroll
      for (int h=0;h<2;h++){
        int gm = row0 + wm0 + mt*16 + gid + h*8;
        if (gm>=M) continue;
        long long base = (long long)gm*ldc;
#pragma unroll
        for (int nt=0;nt<4;nt++){
          int gn = col0 + wn0 + nt*8 + tq*2;
          if (gn>=N) continue;
          float v0 = alpha*acc[mt][nt][h*2+0];
          float v1 = alpha*acc[mt][nt][h*2+1];
          if (bias){ v0 += bias[gn]; if (gn+1<N) v1 += bias[gn+1]; }
          if (Cr)  { v0 += Cr[base+gn]; if (gn+1<N) v1 += Cr[base+gn+1]; }
          if (gn+1<N){
            float2 st2; st2.x=v0; st2.y=v1; *(float2*)&C[base+gn]=st2;
            if (Ch){
              uint32_t hh, ll; cvt2(v0, v1, hh, ll);
              *(uint32_t*)&Ch[base+gn] = hh;
              *(uint32_t*)&Cl[base+gn] = ll;
            }
          } else {
            C[base+gn]=v0;
            if (Ch){ __nv_bfloat16 hh, ll; cvt1(v0, hh, ll); Ch[base+gn]=hh; Cl[base+gn]=ll; }
          }
        }
      }
}

#define P_NONE  (1<<30), 0LL, 1, 0LL, 0LL
#define P_PLAIN(s) (1<<30), 0LL, 1, (long long)(s), 0LL

static void run_hgemm(const __nv_bfloat16* Ah, const __nv_bfloat16* Al,
                      const __nv_bfloat16* Bh, const __nv_bfloat16* Bl,
                      const float* bias, const float* Cin, float* C,
                      __nv_bfloat16* Ch, __nv_bfloat16* Cl,
                      int M, int N, int K, int lda, int ldb, int ldc,
                      int aD1, long long aS1, int aD2, long long aS2, long long aS3,
                      int bD1, long long bS1, int bD2, long long bS2, long long bS3,
                      long long sCin, long long sC, int batch, float alpha, int addC)
{
    long long b128 = (long long)((N+127)/128)*((M+127)/128)*batch;
    if (M >= 96 && b128 >= 90) {
        constexpr int SM = 3*(2*128+256)*40*2;   // 122880 B
        cudaFuncSetAttribute(hgemm3<128>, cudaFuncAttributeMaxDynamicSharedMemorySize, SM);
        dim3 grid((N+127)/128, (M+127)/128, batch);
        hgemm3<128><<<grid, 256, SM>>>(Ah,Al,Bh,Bl,bias,Cin,C,Ch,Cl,M,N,K,lda,ldb,ldc,
            aD1,aS1,aD2,aS2,aS3,bD1,bS1,bD2,bS2,bS3,sCin,sC,alpha,addC);
    } else {
        constexpr int SM = 3*(2*64+256)*40*2;    // 92160 B
        cudaFuncSetAttribute(hgemm3<64>, cudaFuncAttributeMaxDynamicSharedMemorySize, SM);
        dim3 grid((N+127)/128, (M+63)/64, batch);
        hgemm3<64><<<grid, 128, SM>>>(Ah,Al,Bh,Bl,bias,Cin,C,Ch,Cl,M,N,K,lda,ldb,ldc,
            aD1,aS1,aD2,aS2,aS3,bD1,bS1,bD2,bS2,bS3,sCin,sC,alpha,addC);
    }
}

// ======= transpose-convert v2: fp32 [K][N] -> bf16 hi/lo [N][Kp]; 64x32 tiles, uint32 stores =======
__global__ void tconv(const float* __restrict__ in, __nv_bfloat16* __restrict__ oh,
                      __nv_bfloat16* __restrict__ ol,
                      int K, int N, int Kp, long long sIn, long long sOut)
{
    __shared__ float t[64][33];
    int z = blockIdx.z;
    const float* I = in + (long long)z * sIn;
    __nv_bfloat16* OH = oh + (long long)z * sOut;
    __nv_bfloat16* OL = ol + (long long)z * sOut;
    int kb = blockIdx.y * 64, nb = blockIdx.x * 32;
    int tx = threadIdx.x;
    for (int i = threadIdx.y; i < 64; i += 8) {
        int k = kb + i, n = nb + tx;
        t[i][tx] = (k < K && n < N) ? I[(long long)k*N + n] : 0.f;
    }
    __syncthreads();
    int k2 = kb + tx*2;
    bool kok = (k2 + 1 < Kp) || (k2 < Kp);   // Kp even in all call sites -> pair never straddles
    if (k2 < Kp) {
        for (int i = threadIdx.y; i < 32; i += 8) {
            int n = nb + i;
            if (n >= N) continue;
            uint32_t hh, ll;
            cvt2(t[tx*2][i], t[tx*2+1][i], hh, ll);
            *(uint32_t*)&OH[(long long)n*Kp + k2] = hh;
            *(uint32_t*)&OL[(long long)n*Kp + k2] = ll;
        }
    }
    (void)kok;
}

// ---------------- fp32 fallback GEMM (final head, M=8) ----------------
__global__ __launch_bounds__(64)
void sgemm_s(const float* __restrict__ A, const float* __restrict__ B,
             const float* __restrict__ bias, float* __restrict__ C,
             int M, int N, int K, int lda, int ldb, int ldc)
{
    constexpr int BK = 16;
    __shared__ float As[BK][36];
    __shared__ float Bs[BK][36];
    int row0 = blockIdx.y*32, col0 = blockIdx.x*32;
    int tid = threadIdx.x;
    int tx = tid % 8, ty = tid / 8;
    float acc[4][4];
#pragma unroll
    for (int i=0;i<4;i++)
#pragma unroll
      for (int j=0;j<4;j++) acc[i][j]=0.f;
    for (int k0 = 0; k0 < K; k0 += BK) {
        for (int e = tid; e < 32*BK/4; e += 64) {
            int mm = e >> 2, c4 = e & 3;
            int gm = row0+mm, gk = k0+c4*4;
            float4 v = make_float4(0.f,0.f,0.f,0.f);
            if (gm < M && gk < K) v = *(const float4*)&A[(long long)gm*lda+gk];
            As[c4*4+0][mm]=v.x; As[c4*4+1][mm]=v.y; As[c4*4+2][mm]=v.z; As[c4*4+3][mm]=v.w;
        }
        for (int e = tid; e < BK*8; e += 64) {
            int kk = e / 8, n4 = e % 8;
            int gk = k0+kk, gn = col0+n4*4;
            float4 v = make_float4(0.f,0.f,0.f,0.f);
            if (gk < K) {
                if (gn+3 < N) v = *(const float4*)&B[(long long)gk*ldb+gn];
                else {
                    const float* p = &B[(long long)gk*ldb];
                    if (gn<N)v.x=p[gn]; if (gn+1<N)v.y=p[gn+1];
                    if (gn+2<N)v.z=p[gn+2]; if (gn+3<N)v.w=p[gn+3];
                }
            }
            Bs[kk][n4*4+0]=v.x; Bs[kk][n4*4+1]=v.y; Bs[kk][n4*4+2]=v.z; Bs[kk][n4*4+3]=v.w;
        }
        __syncthreads();
#pragma unroll
        for (int kk = 0; kk < BK; kk++) {
            float a[4], b[4];
#pragma unroll
            for (int i=0;i<4;i++) a[i]=As[kk][ty*4+i];
#pragma unroll
            for (int j=0;j<4;j++) b[j]=Bs[kk][tx*4+j];
#pragma unroll
            for (int i=0;i<4;i++)
#pragma unroll
              for (int j=0;j<4;j++) acc[i][j]+=a[i]*b[j];
        }
        __syncthreads();
    }
#pragma unroll
    for (int i=0;i<4;i++){
        int gm = row0+ty*4+i;
        if (gm >= M) continue;
#pragma unroll
        for (int j=0;j<4;j++){
            int gn = col0+tx*4+j;
            if (gn >= N) continue;
            float v = acc[i][j];
            if (bias) v += bias[gn];
            C[(long long)gm*ldc+gn] = v;
        }
    }
}

// ---------------- elementwise kernels ----------------
__global__ void patch_gather2(const float* __restrict__ img,
                              __nv_bfloat16* __restrict__ oh, __nv_bfloat16* __restrict__ ol) {
    int idx = blockIdx.x*blockDim.x + threadIdx.x;
    int total = BATCH*NPATCH*PK;
    if (idx >= total) return;
    int k = idx % PK;
    int p = (idx / PK) % NPATCH;
    int b = idx / (PK*NPATCH);
    int c  = k % 3;
    int pj = (k/3) % 16;
    int pi = k / 48;
    int i = p / 14, j = p % 14;
    float v = img[(((long long)b*3 + c)*224 + (i*16+pi))*224 + (j*16+pj)];
    __nv_bfloat16 h, l; cvt1(v, h, l);
    oh[idx] = h; ol[idx] = l;
}

__global__ void assemble_x_kernel(const float* __restrict__ xp, const float* __restrict__ cls,
                                  float* __restrict__ x) {
    int idx = blockIdx.x*blockDim.x + threadIdx.x;
    int total = BATCH*SEQ*DIM;
    if (idx >= total) return;
    int d = idx % DIM;
    int m = (idx / DIM) % SEQ;
    int b = idx / (DIM*SEQ);
    x[idx] = (m == 0) ? cls[d] : xp[((long long)b*NPATCH + (m-1))*DIM + d];
}

__global__ void rms_part_kernel(const float* __restrict__ x, float* __restrict__ red) {
    int b = blockIdx.y, ch = blockIdx.x;
    const int per_batch = SEQ*DIM;
    const int chunk = per_batch/32;
    const float4* p = (const float4*)(x + (long long)b*per_batch + ch*chunk);
    float s = 0.f;
    for (int i = threadIdx.x; i < chunk/4; i += 256) {
        float4 v = p[i];
        s += v.x*v.x + v.y*v.y + v.z*v.z + v.w*v.w;
    }
    __shared__ float sm[256];
    sm[threadIdx.x] = s; __syncthreads();
    for (int o = 128; o > 0; o >>= 1) { if (threadIdx.x < o) sm[threadIdx.x] += sm[threadIdx.x+o]; __syncthreads(); }
    if (threadIdx.x == 0) red[b*32 + ch] = sm[0];
}
__global__ void rms_fin_kernel(const float* __restrict__ red, float* __restrict__ fac) {
    int b = threadIdx.x / 32, lane = threadIdx.x % 32;
    float v = red[b*32 + lane];
    for (int o = 16; o; o >>= 1) v += __shfl_xor_sync(0xffffffffu, v, o);
    if (lane == 0) fac[b] = sqrtf((float)(SEQ*DIM) / v);
}
__global__ void rms_apply2(float* __restrict__ x, const float* __restrict__ fac,
                           const float* __restrict__ scale,
                           uint2* __restrict__ xh, uint2* __restrict__ xl) {
    int idx = blockIdx.x*blockDim.x + threadIdx.x;
    const int per4 = SEQ*DIM/4;
    int total = BATCH*per4;
    if (idx >= total) return;
    int b = idx / per4, s4 = idx % per4;
    float f = fac[b];
    float4 v = ((float4*)x)[idx];
    float4 sc = ((const float4*)scale)[s4];
    v.x *= f*sc.x; v.y *= f*sc.y; v.z *= f*sc.z; v.w *= f*sc.w;
    ((float4*)x)[idx] = v;
    uint2 h, l; cvt4(v, h, l);
    xh[idx] = h; xl[idx] = l;
}

// rope table (bit-identical per-element math)
__global__ void rope_tab(float2* __restrict__ tab, int M, int half, float cc) {
    int idx = blockIdx.x*blockDim.x + threadIdx.x;
    if (idx >= M*half) return;
    int i = idx % half, m = idx / half;
    float theta = exp2f(cc * ((float)i - 1.f));
    float ang = (float)m * theta;
    float s, c;
    sincosf(ang, &s, &c);
    tab[idx] = make_float2(c, s);
}

// table-driven rope; separate output row stride ldo (pad region never written)
__global__ void rope3(const float* __restrict__ q, const float* __restrict__ k,
                      __nv_bfloat16* __restrict__ qh, __nv_bfloat16* __restrict__ ql,
                      __nv_bfloat16* __restrict__ kh, __nv_bfloat16* __restrict__ kl,
                      const float2* __restrict__ tab, int Z, int M, int D, int ldo) {
    int half = D / 2;
    long long total = (long long)Z * M * half;
    long long idx = (long long)blockIdx.x*blockDim.x + threadIdx.x;
    if (idx >= total) return;
    int i = (int)(idx % half);
    int m = (int)((idx / half) % M);
    long long z = idx / ((long long)half * M);
    float2 cs = tab[m*half + i];
    float c = cs.x, s = cs.y;
    long long bi = ((z*M) + m) * (long long)D + 2*i;
    long long bo = ((z*M) + m) * (long long)ldo + 2*i;
    float xe, xo, re, ro;
    uint32_t h, l;
    xe = q[bi]; xo = q[bi+1];
    re = xe*c + xo*s; ro = -xe*s + xo*c;
    cvt2(re, ro, h, l);
    *(uint32_t*)&qh[bo] = h; *(uint32_t*)&ql[bo] = l;
    xe = k[bi]; xo = k[bi+1];
    re = xe*c + xo*s; ro = -xe*s + xo*c;
    cvt2(re, ro, h, l);
    *(uint32_t*)&kh[bo] = h; *(uint32_t*)&kl[bo] = l;
}

// split-K reduce for token scores: ts[b][ij] = scale * sum_c ts4[b*4+c][ij]
__global__ void tsred_kernel(const float4* __restrict__ in, float4* __restrict__ outp, float scale) {
    int idx = blockIdx.x*blockDim.x + threadIdx.x;
    const int per = CDIM*CDIM/4;   // 1024
    int total = BATCH*per;
    if (idx >= total) return;
    int b = idx / per, ij = idx % per;
    float4 a0 = in[((long long)b*4+0)*per + ij];
    float4 a1 = in[((long long)b*4+1)*per + ij];
    float4 a2 = in[((long long)b*4+2)*per + ij];
    float4 a3 = in[((long long)b*4+3)*per + ij];
    float4 r;
    r.x = scale*(((a0.x + a1.x) + a2.x) + a3.x);
    r.y = scale*(((a0.y + a1.y) + a2.y) + a3.y);
    r.z = scale*(((a0.z + a1.z) + a2.z) + a3.z);
    r.w = scale*(((a0.w + a1.w) + a2.w) + a3.w);
    outp[idx] = r;
}

__global__ void softmax2(float* __restrict__ s,
                         __nv_bfloat16* __restrict__ ph, __nv_bfloat16* __restrict__ pl,
                         int rows, int L, int ld) {
    int warp = (blockIdx.x*blockDim.x + threadIdx.x) / 32;
    int lane = threadIdx.x % 32;
    if (warp >= rows) return;
    long long ro = (long long)warp * ld;
    float* row = s + ro;
    float mx = -1e30f;
    for (int i = lane; i < L; i += 32) mx = fmaxf(mx, row[i]);
    for (int o = 16; o; o >>= 1) mx = fmaxf(mx, __shfl_xor_sync(0xffffffffu, mx, o));
    float sum = 0.f;
    for (int i = lane; i < L; i += 32) { float e = __expf(row[i]-mx); row[i] = e; sum += e; }
    for (int o = 16; o; o >>= 1) sum += __shfl_xor_sync(0xffffffffu, sum, o);
    float inv = 1.f / sum;
    for (int i = lane; i < ld; i += 32) {
        float v = (i < L) ? row[i]*inv : 0.f;
        __nv_bfloat16 h, l; cvt1(v, h, l);
        ph[ro + i] = h; pl[ro + i] = l;
    }
}

// x[b][m][:] += bias + sum_h part[(h*8+b)][m][:]
__global__ void attn_reduce_kernel(const float* __restrict__ part,
                                   const float* __restrict__ bias,
                                   float* __restrict__ x) {
    int idx = blockIdx.x*blockDim.x + threadIdx.x;
    const int D4 = DIM/4;
    int total = BATCH*SEQ*D4;
    if (idx >= total) return;
    int d4 = idx % D4;
    int m  = (idx / D4) % SEQ;
    int b  = idx / (D4*SEQ);
    float4 acc = ((float4*)x)[idx];
    float4 bb = ((const float4*)bias)[d4];
    acc.x += bb.x; acc.y += bb.y; acc.z += bb.z; acc.w += bb.w;
#pragma unroll
    for (int h = 0; h < HEADS; h++) {
        float4 p = ((const float4*)part)[((long long)(h*BATCH+b)*SEQ + m)*D4 + d4];
        acc.x += p.x; acc.y += p.y; acc.z += p.z; acc.w += p.w;
    }
    ((float4*)x)[idx] = acc;
}

__global__ void x_to_y2(const float* __restrict__ x, float* __restrict__ y,
                        __nv_bfloat16* __restrict__ yh, __nv_bfloat16* __restrict__ yl) {
    int idx = blockIdx.x*blockDim.x + threadIdx.x;
    int total = BATCH*CDIM*TDIM;
    if (idx >= total) return;
    int t = idx % TDIM;
    int c = (idx / TDIM) % CDIM;
    int b = idx / (TDIM*CDIM);
    int f = t / SEQ, mm = t % SEQ;
    float v = x[((long long)b*SEQ + mm)*DIM + c*8 + f];
    y[idx] = v;
    __nv_bfloat16 h, l; cvt1(v, h, l);
    yh[idx] = h; yl[idx] = l;
}

__global__ void y_to_x_kernel(const float* __restrict__ y, float* __restrict__ x) {
    int idx = blockIdx.x*blockDim.x + threadIdx.x;
    int total = BATCH*SEQ*DIM;
    if (idx >= total) return;
    int d  = idx % DIM;
    int mm = (idx / DIM) % SEQ;
    int b  = idx / (DIM*SEQ);
    int c = d >> 3, f = d & 7;
    x[idx] = y[((long long)b*CDIM + c)*TDIM + f*SEQ + mm];
}

__global__ void cls_ln_kernel(const float* __restrict__ x, const float* __restrict__ g,
                              const float* __restrict__ be, float* __restrict__ out) {
    int b = blockIdx.x, t = threadIdx.x;
    const float* row = x + (long long)b*SEQ*DIM;
    __shared__ float red[256];
    float s = 0.f;
    for (int i = t; i < DIM; i += 256) s += row[i];
    red[t] = s; __syncthreads();
    for (int o = 128; o > 0; o >>= 1) { if (t < o) red[t] += red[t+o]; __syncthreads(); }
    float mu = red[0] / DIM; __syncthreads();
    float v = 0.f;
    for (int i = t; i < DIM; i += 256) { float d = row[i]-mu; v += d*d; }
    red[t] = v; __syncthreads();
    for (int o = 128; o > 0; o >>= 1) { if (t < o) red[t] += red[t+o]; __syncthreads(); }
    float inv = rsqrtf(red[0]/DIM + 1e-5f);
    for (int i = t; i < DIM; i += 256) out[b*DIM + i] = (row[i]-mu)*inv*g[i] + be[i];
}

static inline int nblk(long long n, int t) { return (int)((n + t - 1) / t); }

extern "C" void kernel_launch(void* const* d_in, const int* in_sizes, int n_in,
                              void* d_out, int out_size) {
    const float* img       = (const float*)d_in[0];
    const float* patch_W   = (const float*)d_in[1];
    const float* patch_b   = (const float*)d_in[2];
    const float* cls_token = (const float*)d_in[3];
    const float* rms_scale = (const float*)d_in[4];
    const float* Wq        = (const float*)d_in[5];
    const float* Wk        = (const float*)d_in[6];
    const float* Wv        = (const float*)d_in[7];
    const float* attn_W    = (const float*)d_in[8];
    const float* attn_b    = (const float*)d_in[9];
    const float* tWq       = (const float*)d_in[10];
    const float* tWk       = (const float*)d_in[11];
    const float* tWv       = (const float*)d_in[12];
    const float* ln_g      = (const float*)d_in[13];
    const float* ln_b      = (const float*)d_in[14];
    const float* head_W    = (const float*)d_in[15];
    const float* head_b    = (const float*)d_in[16];
    float* out = (float*)d_out;

    float *pxp,*px,*pqkv,*ps,*po,*pot,*py,*ptqkv,*pts,*pts4,*pf,*pred,*pcls;
    float2 *ptab1,*ptab2;
    cudaGetSymbolAddress((void**)&pxp,  g_xp);
    cudaGetSymbolAddress((void**)&px,   g_x);
    cudaGetSymbolAddress((void**)&pqkv, g_qkv);
    cudaGetSymbolAddress((void**)&ps,   g_sc);
    cudaGetSymbolAddress((void**)&po,   g_o);
    cudaGetSymbolAddress((void**)&pot,  g_ot);
    cudaGetSymbolAddress((void**)&py,   g_y);
    cudaGetSymbolAddress((void**)&ptqkv,g_tqkv);
    cudaGetSymbolAddress((void**)&pts,  g_ts);
    cudaGetSymbolAddress((void**)&pts4, g_ts4);
    cudaGetSymbolAddress((void**)&pf,   g_fac);
    cudaGetSymbolAddress((void**)&pred, g_red);
    cudaGetSymbolAddress((void**)&pcls, g_cls);
    cudaGetSymbolAddress((void**)&ptab1, g_tab1);
    cudaGetSymbolAddress((void**)&ptab2, g_tab2);

    __nv_bfloat16 *path_h,*path_l,*xh,*xl,*qh,*ql,*kh,*kl,*ph,*pl,*oh,*ol;
    __nv_bfloat16 *yh,*yl,*tqh,*tql,*tkh,*tkl,*tsh,*tsl;
    __nv_bfloat16 *pwh,*pwl,*wAh,*wAl,*awh,*awl,*twAh,*twAl,*vth,*vtl,*tvth,*tvtl;
    cudaGetSymbolAddress((void**)&path_h, g_path_h); cudaGetSymbolAddress((void**)&path_l, g_path_l);
    cudaGetSymbolAddress((void**)&xh,  g_xh);  cudaGetSymbolAddress((void**)&xl,  g_xl);
    cudaGetSymbolAddress((void**)&qh,  g_qh);  cudaGetSymbolAddress((void**)&ql,  g_ql);
    cudaGetSymbolAddress((void**)&kh,  g_kh);  cudaGetSymbolAddress((void**)&kl,  g_kl);
    cudaGetSymbolAddress((void**)&ph,  g_ph);  cudaGetSymbolAddress((void**)&pl,  g_pl);
    cudaGetSymbolAddress((void**)&oh,  g_oh);  cudaGetSymbolAddress((void**)&ol,  g_ol);
    cudaGetSymbolAddress((void**)&yh,  g_yh);  cudaGetSymbolAddress((void**)&yl,  g_yl);
    cudaGetSymbolAddress((void**)&tqh, g_tqh); cudaGetSymbolAddress((void**)&tql, g_tql);
    cudaGetSymbolAddress((void**)&tkh, g_tkh); cudaGetSymbolAddress((void**)&tkl, g_tkl);
    cudaGetSymbolAddress((void**)&tsh, g_tsh); cudaGetSymbolAddress((void**)&tsl, g_tsl);
    cudaGetSymbolAddress((void**)&pwh,  g_pwh);  cudaGetSymbolAddress((void**)&pwl,  g_pwl);
    cudaGetSymbolAddress((void**)&wAh,  g_wAh);  cudaGetSymbolAddress((void**)&wAl,  g_wAl);
    cudaGetSymbolAddress((void**)&awh,  g_awh);  cudaGetSymbolAddress((void**)&awl,  g_awl);
    cudaGetSymbolAddress((void**)&twAh, g_twAh); cudaGetSymbolAddress((void**)&twAl, g_twAl);
    cudaGetSymbolAddress((void**)&vth,  g_vth);  cudaGetSymbolAddress((void**)&vtl,  g_vtl);
    cudaGetSymbolAddress((void**)&tvth, g_tvth); cudaGetSymbolAddress((void**)&tvtl, g_tvtl);

    const long long sQH  = (long long)SEQ*DIM;
    const long long sSSp = (long long)SEQ*SEQP;
    const long long sY   = (long long)CDIM*TDIM;
    const long long sYp  = (long long)CDIM*TDIMP;
    const long long sTS  = (long long)CDIM*CDIM;
    const long long sW   = (long long)DIM*DIM;
    const long long sVT  = (long long)DIM*SEQP;
    const long long sTVT = (long long)TDIM*CDIM;
    const long long sTW  = (long long)TDIM*TDIM;
    const float scale1 = (float)(1.0/sqrt(512.0));
    const float scale2 = (float)(1.0/sqrt(1576.0));
    const float cc1 = (float)(-2.0*log2(10000.0)/512.0);
    const float cc2 = (float)(-2.0*log2(10000.0)/1576.0);
    dim3 tcb(32, 8);

    // ---- rope tables ----
    rope_tab<<<nblk(SEQ*256,256),256>>>(ptab1, SEQ, 256, cc1);
    rope_tab<<<nblk(CDIM*788,256),256>>>(ptab2, CDIM, 788, cc2);

    // ---- weight pre-conversion (tconv v2: grid.y = ceil(Kp/64)) ----
    tconv<<<dim3(DIM/32, PK/64, 1), tcb>>>(patch_W, pwh, pwl, PK, DIM, PK, 0, 0);
    for (int l = 0; l < 2; l++) {
        const float* srcs[3] = {Wq, Wk, Wv};
        for (int w = 0; w < 3; w++) {
            tconv<<<dim3(16, 8, 8), tcb>>>(srcs[w] + (long long)l*8*sW,
                                           wAh + ((long long)l*24 + w*8)*sW,
                                           wAl + ((long long)l*24 + w*8)*sW,
                                           DIM, DIM, DIM, sW, sW);
        }
        const float* tsrcs[3] = {tWq, tWk, tWv};
        for (int w = 0; w < 3; w++) {
            tconv<<<dim3(50, 25, 1), tcb>>>(tsrcs[w] + (long long)l*sTW,
                                            twAh + ((long long)l*3 + w)*sTW,
                                            twAl + ((long long)l*3 + w)*sTW,
                                            TDIM, TDIM, TDIM, 0, 0);
        }
    }
    tconv<<<dim3(16, 8, 16), tcb>>>(attn_W, awh, awl, DIM, DIM, DIM, sW, sW);

    // ---- patch embedding ----
    patch_gather2<<<nblk((long long)BATCH*NPATCH*PK,256),256>>>(img, path_h, path_l);
    run_hgemm(path_h, path_l, pwh, pwl, patch_b, 0, pxp, 0, 0,
              BATCH*NPATCH, DIM, PK, PK, PK, DIM,
              P_NONE, P_NONE, 0, 0, 1, 1.f, 0);
    assemble_x_kernel<<<nblk((long long)BATCH*SEQ*DIM,256),256>>>(pxp, cls_token, px);

    for (int l = 0; l < 2; l++) {
        const float* scale_l = rms_scale + (long long)l*SEQ*DIM;

        // rmsnorm #1 (+split)
        rms_part_kernel<<<dim3(32,BATCH),256>>>(px, pred);
        rms_fin_kernel<<<1,256>>>(pred, pf);
        rms_apply2<<<nblk((long long)BATCH*SEQ*DIM/4,256),256>>>(px, pf, scale_l,
                                                                 (uint2*)xh, (uint2*)xl);

        // fused QKV, batch folded into M: M=1576, z = w*8+h (24 batches)
        run_hgemm(xh, xl, wAh + (long long)l*24*sW, wAl + (long long)l*24*sW, 0, 0, pqkv, 0, 0,
                  BATCH*SEQ, DIM, DIM, DIM, DIM, DIM,
                  P_NONE,
                  8, 8*sW, 8, 0LL, sW,
                  0, 8*sQH, 24, 1.f, 0);

        // v -> vT split [DIM][SEQP]
        tconv<<<dim3(16, 4, 64), tcb>>>(pqkv + 128*sQH, vth, vtl, SEQ, DIM, SEQP, sQH, sVT);

        // RoPE -> split q,k (ldo = DIM, unpadded)
        rope3<<<nblk((long long)64*SEQ*(DIM/2),256),256>>>(pqkv, pqkv + 64*sQH,
                                                           qh, ql, kh, kl, ptab1, 64, SEQ, DIM, DIM);

        // scores
        run_hgemm(qh, ql, kh, kl, 0, 0, ps, 0, 0,
                  SEQ, SEQ, DIM, DIM, DIM, SEQP,
                  P_PLAIN(sQH), P_PLAIN(sQH), 0, sSSp, 64, scale1, 0);
        softmax2<<<nblk((long long)64*SEQ*32,256),256>>>(ps, ph, pl, 64*SEQ, SEQ, SEQP);

        // o = p @ v (epilogue emits split oh/ol)
        run_hgemm(ph, pl, vth, vtl, 0, 0, po, oh, ol,
                  SEQ, DIM, SEQP, SEQP, SEQP, DIM,
                  P_PLAIN(sSSp), P_PLAIN(sVT), 0, sQH, 64, 1.f, 0);

        // proj partials, batch folded into M: M=1576, z=h (8 batches)
        run_hgemm(oh, ol, awh + (long long)l*8*sW, awl + (long long)l*8*sW, 0, 0, pot, 0, 0,
                  BATCH*SEQ, DIM, DIM, DIM, DIM, DIM,
                  P_PLAIN(8*sQH), P_PLAIN(sW), 0, 8*sQH, 8, 1.f, 0);
        attn_reduce_kernel<<<nblk((long long)BATCH*SEQ*DIM/4,256),256>>>(pot, attn_b + l*DIM, px);

        // rmsnorm #2 (+split)
        rms_part_kernel<<<dim3(32,BATCH),256>>>(px, pred);
        rms_fin_kernel<<<1,256>>>(pred, pf);
        rms_apply2<<<nblk((long long)BATCH*SEQ*DIM/4,256),256>>>(px, pf, scale_l,
                                                                 (uint2*)xh, (uint2*)xl);

        // token-mixing
        x_to_y2<<<nblk((long long)BATCH*CDIM*TDIM,256),256>>>(px, py, yh, yl);

        // fused token QKV, batch folded into M: M=512, z=w (3 batches)
        run_hgemm(yh, yl, twAh + (long long)l*3*sTW, twAl + (long long)l*3*sTW, 0, 0, ptqkv, 0, 0,
                  BATCH*CDIM, TDIM, TDIM, TDIM, TDIM, TDIM,
                  P_NONE, P_PLAIN(sTW), 0, 8*sY, 3, 1.f, 0);

        // tv -> tvT split
        tconv<<<dim3(50, 1, 8), tcb>>>(ptqkv + 16*sY, tvth, tvtl, CDIM, TDIM, CDIM, sY, sTVT);

        // RoPE -> split tq,tk into PADDED buffers (ldo = 1600, pad stays zero)
        rope3<<<nblk((long long)BATCH*CDIM*(TDIM/2),256),256>>>(ptqkv, ptqkv + 8*sY,
                                                                 tqh, tql, tkh, tkl,
                                                                 ptab2, BATCH, CDIM, TDIM, TDIMP);

        // token scores, split-K x4 (chunks of 400 over padded 1600): z = b*4+c -> 32 blocks
        run_hgemm(tqh, tql, tkh, tkl, 0, 0, pts4, 0, 0,
                  CDIM, CDIM, 400, TDIMP, TDIMP, CDIM,
                  4, sYp, 1, 400LL, 0LL,
                  4, sYp, 1, 400LL, 0LL,
                  0, sTS, 32, 1.f, 0);
        tsred_kernel<<<nblk((long long)BATCH*CDIM*CDIM/4,256),256>>>((const float4*)pts4,
                                                                     (float4*)pts, scale2);
        softmax2<<<nblk((long long)BATCH*CDIM*32,256),256>>>(pts, tsh, tsl,
                                                             BATCH*CDIM, CDIM, CDIM);

        // y += p @ tv
        run_hgemm(tsh, tsl, tvth, tvtl, 0, py, py, 0, 0,
                  CDIM, TDIM, CDIM, CDIM, CDIM, TDIM,
                  P_PLAIN(sTS), P_PLAIN(sTVT), sY, sY, BATCH, 1.f, 1);

        y_to_x_kernel<<<nblk((long long)BATCH*SEQ*DIM,256),256>>>(py, px);
    }

    // ---- final: cls layernorm + head ----
    cls_ln_kernel<<<BATCH,256>>>(px, ln_g, ln_b, pcls);
    {
        dim3 grid((NCLS+31)/32, 1, 1);
        sgemm_s<<<grid, 64>>>(pcls, head_W, head_b, out, BATCH, NCLS, DIM, DIM, NCLS, NCLS);
    }
}

// round 17
// speedup vs baseline: 2.2500x; 1.3687x over previous
#include <cuda_runtime.h>
#include <cuda_fp16.h>
#include <math.h>
#include <stdint.h>

#define BATCH 8
#define HEADS 8
#define DIM 512
#define SEQ 197
#define SEQP 208
#define NPATCH 196
#define PK 768
#define CDIM 64
#define TDIM 1576
#define TDIMP 1600
#define NCLS 1000

// ---------------- fp32 scratch ----------------
__device__ float g_xp[BATCH*NPATCH*DIM];
__device__ float g_x[BATCH*SEQ*DIM];
__device__ float g_qkv[192*SEQ*DIM];          // [w][h][b][SEQ][DIM]
__device__ float g_sc[BATCH*HEADS*SEQ*SEQP];
__device__ float g_o[BATCH*HEADS*SEQ*DIM];
__device__ float g_ot[BATCH*SEQ*HEADS*DIM];   // proj partials [h][b][SEQ][DIM]
__device__ float g_y[BATCH*CDIM*TDIM];
__device__ float g_tqkv[24*CDIM*TDIM];        // [w][b][CDIM][TDIM]
__device__ float g_ts[BATCH*CDIM*CDIM];
__device__ float g_ts4[32*CDIM*CDIM];         // split-K partials
__device__ float g_fac[BATCH];
__device__ float g_red[BATCH*32];
__device__ float g_cls[BATCH*DIM];
__device__ float2 g_tab1[SEQ*256];
__device__ float2 g_tab2[CDIM*788];

// ---------------- fp16 hi/lo split operands (K-major) ----------------
__device__ __half g_path_h[BATCH*NPATCH*PK],  g_path_l[BATCH*NPATCH*PK];
__device__ __half g_xh[BATCH*SEQ*DIM],        g_xl[BATCH*SEQ*DIM];
__device__ __half g_qh[BATCH*HEADS*SEQ*DIM],  g_ql[BATCH*HEADS*SEQ*DIM];
__device__ __half g_kh[BATCH*HEADS*SEQ*DIM];
__device__ __half g_ph[BATCH*HEADS*SEQ*SEQP], g_pl[BATCH*HEADS*SEQ*SEQP];
__device__ __half g_oh[BATCH*HEADS*SEQ*DIM],  g_ol[BATCH*HEADS*SEQ*DIM];
__device__ __half g_yh[BATCH*CDIM*TDIM],      g_yl[BATCH*CDIM*TDIM];
__device__ __half g_tqh[BATCH*CDIM*TDIMP],    g_tql[BATCH*CDIM*TDIMP];   // padded; pad stays zero
__device__ __half g_tkh[BATCH*CDIM*TDIMP];
__device__ __half g_tsh[BATCH*CDIM*CDIM],     g_tsl[BATCH*CDIM*CDIM];
// weights (hi only; used as B)
__device__ __half g_pwh[DIM*PK];
__device__ __half g_wAh[2*3*8*DIM*DIM];       // [l][w][h]
__device__ __half g_awh[16*DIM*DIM];
__device__ __half g_twAh[2*3*TDIM*TDIM];      // [l][w]
__device__ __half g_vth[64*DIM*SEQP];
__device__ __half g_tvth[8*TDIM*CDIM];

// ---------------- helpers ----------------
__device__ __forceinline__ void cvt4(float4 v, uint2 &h, uint2 &l){
    __half ax=__float2half_rn(v.x), ay=__float2half_rn(v.y);
    __half az=__float2half_rn(v.z), aw=__float2half_rn(v.w);
    __half2 h0; h0.x=ax; h0.y=ay;
    __half2 h1; h1.x=az; h1.y=aw;
    h.x=*(unsigned*)&h0; h.y=*(unsigned*)&h1;
    __half2 l0; l0.x=__float2half_rn(v.x-__half2float(ax));
                l0.y=__float2half_rn(v.y-__half2float(ay));
    __half2 l1; l1.x=__float2half_rn(v.z-__half2float(az));
                l1.y=__float2half_rn(v.w-__half2float(aw));
    l.x=*(unsigned*)&l0; l.y=*(unsigned*)&l1;
}
__device__ __forceinline__ void cvt2(float a, float b, uint32_t &h, uint32_t &l){
    __half ha=__float2half_rn(a), hb=__float2half_rn(b);
    __half2 H; H.x=ha; H.y=hb; h=*(uint32_t*)&H;
    __half2 L; L.x=__float2half_rn(a-__half2float(ha));
               L.y=__float2half_rn(b-__half2float(hb)); l=*(uint32_t*)&L;
}
__device__ __forceinline__ void cvt2h(float a, float b, uint32_t &h){
    __half2 H; H.x=__float2half_rn(a); H.y=__float2half_rn(b); h=*(uint32_t*)&H;
}
__device__ __forceinline__ void cvt1(float a, __half &h, __half &l){
    h=__float2half_rn(a);
    l=__float2half_rn(a-__half2float(h));
}
__device__ __forceinline__ void ldsm4(unsigned r[4], const __half* p) {
    unsigned a = (unsigned)__cvta_generic_to_shared(p);
    asm volatile("ldmatrix.sync.aligned.m8n8.x4.shared.b16 {%0,%1,%2,%3}, [%4];"
                 : "=r"(r[0]), "=r"(r[1]), "=r"(r[2]), "=r"(r[3]) : "r"(a));
}
__device__ __forceinline__ void mma16816(float c[4], const unsigned a[4],
                                         unsigned b0, unsigned b1) {
    asm volatile("mma.sync.aligned.m16n8k16.row.col.f32.f16.f16.f32 "
                 "{%0,%1,%2,%3}, {%4,%5,%6,%7}, {%8,%9}, {%0,%1,%2,%3};"
                 : "+f"(c[0]), "+f"(c[1]), "+f"(c[2]), "+f"(c[3])
                 : "r"(a[0]), "r"(a[1]), "r"(a[2]), "r"(a[3]), "r"(b0), "r"(b1));
}
__device__ __forceinline__ void cp16(uint32_t dst, const void* src, bool valid){
    uint64_t g;
    asm("cvta.to.global.u64 %0, %1;" : "=l"(g) : "l"(src));
    int sz = valid ? 16 : 0;
    asm volatile("cp.async.cg.shared.global [%0], [%1], 16, %2;"
                 :: "r"(dst), "l"(g), "r"(sz) : "memory");
}
#define CP_COMMIT() asm volatile("cp.async.commit_group;" ::: "memory")

// ============ fp16 2-term split GEMM: cp.async 3-stage; C = (Ah+Al)@Bh^T ============
// off(z) = (z/D1)*S1 + ((z%D1)/D2)*S2 + (z%D2)*S3  for A and B independently.
template<int BM>
__global__ __launch_bounds__(BM*2)
void hgemm3(const __half* __restrict__ Ah, const __half* __restrict__ Al,
            const __half* __restrict__ Bh,
            const float* __restrict__ bias, const float* __restrict__ Cin,
            float* __restrict__ C,
            __half* __restrict__ Ch, __half* __restrict__ Cl,
            int M, int N, int K, int lda, int ldb, int ldc,
            int aD1, long long aS1, int aD2, long long aS2, long long aS3,
            int bD1, long long bS1, int bD2, long long bS2, long long bS3,
            long long sCin, long long sC, float alpha, int addC)
{
    constexpr int WARPS_M = BM/64;
    constexpr int THREADS = BM*2;
    constexpr int A_CH = BM*4/THREADS;       // 16B chunks per thread (A hi; lo paired)
    constexpr int B_CH = 512/THREADS;        // 16B chunks per thread (B hi)
    constexpr int SH = (2*BM + 128)*40;      // halves per stage
    const int OFF_AL = BM*40, OFF_BH = 2*BM*40;
    extern __shared__ __align__(16) __half sm[];
    uint32_t smem_base = (uint32_t)__cvta_generic_to_shared(sm);

    int z = blockIdx.z;
    long long ao = (long long)(z / aD1)*aS1 + (long long)((z % aD1) / aD2)*aS2
                 + (long long)(z % aD2)*aS3;
    long long bo = (long long)(z / bD1)*bS1 + (long long)((z % bD1) / bD2)*bS2
                 + (long long)(z % bD2)*bS3;
    Ah += ao; Al += ao; Bh += bo;
    long long co = (long long)z * sC;
    C += co;
    if (Ch){ Ch += co; Cl += co; }
    const float* Cr = addC ? Cin + (long long)z * sCin : (const float*)0;

    int row0 = blockIdx.y*BM, col0 = blockIdx.x*128;
    int tid = threadIdx.x, lane = tid & 31, warp = tid >> 5;
    int wm0 = (warp % WARPS_M)*64;
    int wn0 = (warp / WARPS_M)*32;

    float acc[4][4][4];
#pragma unroll
    for (int i=0;i<4;i++)
#pragma unroll
      for (int j=0;j<4;j++)
#pragma unroll
        for (int t=0;t<4;t++) acc[i][j][t]=0.f;

    auto issue = [&](int kt){
        int st = kt % 3;
        uint32_t sb = smem_base + st*SH*2;
        int k0 = kt*32;
#pragma unroll
        for (int t = 0; t < A_CH; t++){
            int idx = tid + t*THREADS;
            int row = idx >> 2, k8 = idx & 3;
            int gm = row0 + row, gk = k0 + k8*8;
            bool v = (gm < M) && (gk < K);
            long long go = (long long)gm*lda + gk;
            uint32_t d = sb + (uint32_t)(row*40 + k8*8)*2;
            cp16(d, v ? Ah+go : Ah, v);
            cp16(d + OFF_AL*2, v ? Al+go : Al, v);
        }
#pragma unroll
        for (int t = 0; t < B_CH; t++){
            int idx = tid + t*THREADS;
            int row = idx >> 2, k8 = idx & 3;
            int gn = col0 + row, gk = k0 + k8*8;
            bool v = (gn < N) && (gk < K);
            long long go = (long long)gn*ldb + gk;
            uint32_t d = sb + (uint32_t)(OFF_BH + row*40 + k8*8)*2;
            cp16(d, v ? Bh+go : Bh, v);
        }
    };

    int r8 = lane&7, s1 = (lane>>3)&1, s2 = lane>>4;
    auto compute = [&](int st, int kk){
        const __half* base = sm + st*SH;
        unsigned ah[4][4], al[4][4], bh[2][4];
#pragma unroll
        for (int mt=0;mt<4;mt++){
            int row = wm0 + mt*16 + r8 + s1*8;
            int col = kk + s2*8;
            ldsm4(ah[mt], base + row*40 + col);
            ldsm4(al[mt], base + OFF_AL + row*40 + col);
        }
#pragma unroll
        for (int np=0;np<2;np++){
            int row = wn0 + np*16 + r8 + s2*8;
            int col = kk + s1*8;
            ldsm4(bh[np], base + OFF_BH + row*40 + col);
        }
#pragma unroll
        for (int mt=0;mt<4;mt++)
#pragma unroll
            for (int nt=0;nt<4;nt++){
                unsigned b0h = bh[nt>>1][(nt&1)*2], b1h = bh[nt>>1][(nt&1)*2+1];
                mma16816(acc[mt][nt], ah[mt], b0h, b1h);
                mma16816(acc[mt][nt], al[mt], b0h, b1h);
            }
    };

    int nk = (K + 31) / 32;
    issue(0); CP_COMMIT();
    if (nk > 1){ issue(1); CP_COMMIT(); }
    for (int kt = 0; kt < nk; kt++){
        if (kt + 1 < nk) { asm volatile("cp.async.wait_group 1;" ::: "memory"); }
        else             { asm volatile("cp.async.wait_group 0;" ::: "memory"); }
        __syncthreads();
        int st = kt % 3;
        compute(st, 0);
        compute(st, 16);
        if (kt + 2 < nk){ issue(kt+2); CP_COMMIT(); }
    }

    // epilogue
    int gid = lane>>2, tq = lane&3;
#pragma unroll
    for (int mt=0;mt<4;mt++)
#pragma unroll
      for (int h=0;h<2;h++){
        int gm = row0 + wm0 + mt*16 + gid + h*8;
        if (gm>=M) continue;
        long long base = (long long)gm*ldc;
#pragma unroll
        for (int nt=0;nt<4;nt++){
          int gn = col0 + wn0 + nt*8 + tq*2;
          if (gn>=N) continue;
          float v0 = alpha*acc[mt][nt][h*2+0];
          float v1 = alpha*acc[mt][nt][h*2+1];
          if (bias){ v0 += bias[gn]; if (gn+1<N) v1 += bias[gn+1]; }
          if (Cr)  { v0 += Cr[base+gn]; if (gn+1<N) v1 += Cr[base+gn+1]; }
          if (gn+1<N){
            float2 st2; st2.x=v0; st2.y=v1; *(float2*)&C[base+gn]=st2;
            if (Ch){
              uint32_t hh, ll; cvt2(v0, v1, hh, ll);
              *(uint32_t*)&Ch[base+gn] = hh;
              *(uint32_t*)&Cl[base+gn] = ll;
            }
          } else {
            C[base+gn]=v0;
            if (Ch){ __half hh, ll; cvt1(v0, hh, ll); Ch[base+gn]=hh; Cl[base+gn]=ll; }
          }
        }
      }
}

#define P_NONE  (1<<30), 0LL, 1, 0LL, 0LL
#define P_PLAIN(s) (1<<30), 0LL, 1, (long long)(s), 0LL

static void run_hgemm(const __half* Ah, const __half* Al, const __half* Bh,
                      const float* bias, const float* Cin, float* C,
                      __half* Ch, __half* Cl,
                      int M, int N, int K, int lda, int ldb, int ldc,
                      int aD1, long long aS1, int aD2, long long aS2, long long aS3,
                      int bD1, long long bS1, int bD2, long long bS2, long long bS3,
                      long long sCin, long long sC, int batch, float alpha, int addC)
{
    long long b128 = (long long)((N+127)/128)*((M+127)/128)*batch;
    if (M >= 96 && b128 >= 90) {
        constexpr int SM = 3*(2*128+128)*40*2;   // 92160 B
        cudaFuncSetAttribute(hgemm3<128>, cudaFuncAttributeMaxDynamicSharedMemorySize, SM);
        dim3 grid((N+127)/128, (M+127)/128, batch);
        hgemm3<128><<<grid, 256, SM>>>(Ah,Al,Bh,bias,Cin,C,Ch,Cl,M,N,K,lda,ldb,ldc,
            aD1,aS1,aD2,aS2,aS3,bD1,bS1,bD2,bS2,bS3,sCin,sC,alpha,addC);
    } else {
        constexpr int SM = 3*(2*64+128)*40*2;    // 61440 B
        cudaFuncSetAttribute(hgemm3<64>, cudaFuncAttributeMaxDynamicSharedMemorySize, SM);
        dim3 grid((N+127)/128, (M+63)/64, batch);
        hgemm3<64><<<grid, 128, SM>>>(Ah,Al,Bh,bias,Cin,C,Ch,Cl,M,N,K,lda,ldb,ldc,
            aD1,aS1,aD2,aS2,aS3,bD1,bS1,bD2,bS2,bS3,sCin,sC,alpha,addC);
    }
}

// ======= transpose-convert: fp32 [K][N] -> fp16 hi [N][Kp]; 64x32 tiles, uint32 stores =======
__global__ void tconv(const float* __restrict__ in, __half* __restrict__ oh,
                      int K, int N, int Kp, long long sIn, long long sOut)
{
    __shared__ float t[64][33];
    int z = blockIdx.z;
    const float* I = in + (long long)z * sIn;
    __half* OH = oh + (long long)z * sOut;
    int kb = blockIdx.y * 64, nb = blockIdx.x * 32;
    int tx = threadIdx.x;
    for (int i = threadIdx.y; i < 64; i += 8) {
        int k = kb + i, n = nb + tx;
        t[i][tx] = (k < K && n < N) ? I[(long long)k*N + n] : 0.f;
    }
    __syncthreads();
    int k2 = kb + tx*2;
    if (k2 < Kp) {
        for (int i = threadIdx.y; i < 32; i += 8) {
            int n = nb + i;
            if (n >= N) continue;
            uint32_t hh;
            cvt2h(t[tx*2][i], t[tx*2+1][i], hh);
            *(uint32_t*)&OH[(long long)n*Kp + k2] = hh;
        }
    }
}

// ---------------- fp32 fallback GEMM (final head, M=8) ----------------
__global__ __launch_bounds__(64)
void sgemm_s(const float* __restrict__ A, const float* __restrict__ B,
             const float* __restrict__ bias, float* __restrict__ C,
             int M, int N, int K, int lda, int ldb, int ldc)
{
    constexpr int BK = 16;
    __shared__ float As[BK][36];
    __shared__ float Bs[BK][36];
    int row0 = blockIdx.y*32, col0 = blockIdx.x*32;
    int tid = threadIdx.x;
    int tx = tid % 8, ty = tid / 8;
    float acc[4][4];
#pragma unroll
    for (int i=0;i<4;i++)
#pragma unroll
      for (int j=0;j<4;j++) acc[i][j]=0.f;
    for (int k0 = 0; k0 < K; k0 += BK) {
        for (int e = tid; e < 32*BK/4; e += 64) {
            int mm = e >> 2, c4 = e & 3;
            int gm = row0+mm, gk = k0+c4*4;
            float4 v = make_float4(0.f,0.f,0.f,0.f);
            if (gm < M && gk < K) v = *(const float4*)&A[(long long)gm*lda+gk];
            As[c4*4+0][mm]=v.x; As[c4*4+1][mm]=v.y; As[c4*4+2][mm]=v.z; As[c4*4+3][mm]=v.w;
        }
        for (int e = tid; e < BK*8; e += 64) {
            int kk = e / 8, n4 = e % 8;
            int gk = k0+kk, gn = col0+n4*4;
            float4 v = make_float4(0.f,0.f,0.f,0.f);
            if (gk < K) {
                if (gn+3 < N) v = *(const float4*)&B[(long long)gk*ldb+gn];
                else {
                    const float* p = &B[(long long)gk*ldb];
                    if (gn<N)v.x=p[gn]; if (gn+1<N)v.y=p[gn+1];
                    if (gn+2<N)v.z=p[gn+2]; if (gn+3<N)v.w=p[gn+3];
                }
            }
            Bs[kk][n4*4+0]=v.x; Bs[kk][n4*4+1]=v.y; Bs[kk][n4*4+2]=v.z; Bs[kk][n4*4+3]=v.w;
        }
        __syncthreads();
#pragma unroll
        for (int kk = 0; kk < BK; kk++) {
            float a[4], b[4];
#pragma unroll
            for (int i=0;i<4;i++) a[i]=As[kk][ty*4+i];
#pragma unroll
            for (int j=0;j<4;j++) b[j]=Bs[kk][tx*4+j];
#pragma unroll
            for (int i=0;i<4;i++)
#pragma unroll
              for (int j=0;j<4;j++) acc[i][j]+=a[i]*b[j];
        }
        __syncthreads();
    }
#pragma unroll
    for (int i=0;i<4;i++){
        int gm = row0+ty*4+i;
        if (gm >= M) continue;
#pragma unroll
        for (int j=0;j<4;j++){
            int gn = col0+tx*4+j;
            if (gn >= N) continue;
            float v = acc[i][j];
            if (bias) v += bias[gn];
            C[(long long)gm*ldc+gn] = v;
        }
    }
}

// ---------------- elementwise kernels ----------------
__global__ void patch_gather2(const float* __restrict__ img,
                              __half* __restrict__ oh, __half* __restrict__ ol) {
    int idx = blockIdx.x*blockDim.x + threadIdx.x;
    int total = BATCH*NPATCH*PK;
    if (idx >= total) return;
    int k = idx % PK;
    int p = (idx / PK) % NPATCH;
    int b = idx / (PK*NPATCH);
    int c  = k % 3;
    int pj = (k/3) % 16;
    int pi = k / 48;
    int i = p / 14, j = p % 14;
    float v = img[(((long long)b*3 + c)*224 + (i*16+pi))*224 + (j*16+pj)];
    __half h, l; cvt1(v, h, l);
    oh[idx] = h; ol[idx] = l;
}

__global__ void assemble_x_kernel(const float* __restrict__ xp, const float* __restrict__ cls,
                                  float* __restrict__ x) {
    int idx = blockIdx.x*blockDim.x + threadIdx.x;
    int total = BATCH*SEQ*DIM;
    if (idx >= total) return;
    int d = idx % DIM;
    int m = (idx / DIM) % SEQ;
    int b = idx / (DIM*SEQ);
    x[idx] = (m == 0) ? cls[d] : xp[((long long)b*NPATCH + (m-1))*DIM + d];
}

__global__ void rms_part_kernel(const float* __restrict__ x, float* __restrict__ red) {
    int b = blockIdx.y, ch = blockIdx.x;
    const int per_batch = SEQ*DIM;
    const int chunk = per_batch/32;
    const float4* p = (const float4*)(x + (long long)b*per_batch + ch*chunk);
    float s = 0.f;
    for (int i = threadIdx.x; i < chunk/4; i += 256) {
        float4 v = p[i];
        s += v.x*v.x + v.y*v.y + v.z*v.z + v.w*v.w;
    }
    __shared__ float sm[256];
    sm[threadIdx.x] = s; __syncthreads();
    for (int o = 128; o > 0; o >>= 1) { if (threadIdx.x < o) sm[threadIdx.x] += sm[threadIdx.x+o]; __syncthreads(); }
    if (threadIdx.x == 0) red[b*32 + ch] = sm[0];
}
__global__ void rms_fin_kernel(const float* __restrict__ red, float* __restrict__ fac) {
    int b = threadIdx.x / 32, lane = threadIdx.x % 32;
    float v = red[b*32 + lane];
    for (int o = 16; o; o >>= 1) v += __shfl_xor_sync(0xffffffffu, v, o);
    if (lane == 0) fac[b] = sqrtf((float)(SEQ*DIM) / v);
}
__global__ void rms_apply2(float* __restrict__ x, const float* __restrict__ fac,
                           const float* __restrict__ scale,
                           uint2* __restrict__ xh, uint2* __restrict__ xl) {
    int idx = blockIdx.x*blockDim.x + threadIdx.x;
    const int per4 = SEQ*DIM/4;
    int total = BATCH*per4;
    if (idx >= total) return;
    int b = idx / per4, s4 = idx % per4;
    float f = fac[b];
    float4 v = ((float4*)x)[idx];
    float4 sc = ((const float4*)scale)[s4];
    v.x *= f*sc.x; v.y *= f*sc.y; v.z *= f*sc.z; v.w *= f*sc.w;
    ((float4*)x)[idx] = v;
    uint2 h, l; cvt4(v, h, l);
    xh[idx] = h; xl[idx] = l;
}

// rope table (bit-identical per-element math)
__global__ void rope_tab(float2* __restrict__ tab, int M, int half, float cc) {
    int idx = blockIdx.x*blockDim.x + threadIdx.x;
    if (idx >= M*half) return;
    int i = idx % half, m = idx / half;
    float theta = exp2f(cc * ((float)i - 1.f));
    float ang = (float)m * theta;
    float s, c;
    sincosf(ang, &s, &c);
    tab[idx] = make_float2(c, s);
}

// table-driven rope; q side -> hi+lo (GEMM A), k side -> hi only (GEMM B)
__global__ void rope3(const float* __restrict__ q, const float* __restrict__ k,
                      __half* __restrict__ qh, __half* __restrict__ ql,
                      __half* __restrict__ kh,
                      const float2* __restrict__ tab, int Z, int M, int D, int ldo) {
    int half = D / 2;
    long long total = (long long)Z * M * half;
    long long idx = (long long)blockIdx.x*blockDim.x + threadIdx.x;
    if (idx >= total) return;
    int i = (int)(idx % half);
    int m = (int)((idx / half) % M);
    long long z = idx / ((long long)half * M);
    float2 cs = tab[m*half + i];
    float c = cs.x, s = cs.y;
    long long bi = ((z*M) + m) * (long long)D + 2*i;
    long long bo = ((z*M) + m) * (long long)ldo + 2*i;
    float xe, xo, re, ro;
    uint32_t h, l;
    xe = q[bi]; xo = q[bi+1];
    re = xe*c + xo*s; ro = -xe*s + xo*c;
    cvt2(re, ro, h, l);
    *(uint32_t*)&qh[bo] = h; *(uint32_t*)&ql[bo] = l;
    xe = k[bi]; xo = k[bi+1];
    re = xe*c + xo*s; ro = -xe*s + xo*c;
    cvt2h(re, ro, h);
    *(uint32_t*)&kh[bo] = h;
}

// split-K reduce for token scores
__global__ void tsred_kernel(const float4* __restrict__ in, float4* __restrict__ outp, float scale) {
    int idx = blockIdx.x*blockDim.x + threadIdx.x;
    const int per = CDIM*CDIM/4;
    int total = BATCH*per;
    if (idx >= total) return;
    int b = idx / per, ij = idx % per;
    float4 a0 = in[((long long)b*4+0)*per + ij];
    float4 a1 = in[((long long)b*4+1)*per + ij];
    float4 a2 = in[((long long)b*4+2)*per + ij];
    float4 a3 = in[((long long)b*4+3)*per + ij];
    float4 r;
    r.x = scale*(((a0.x + a1.x) + a2.x) + a3.x);
    r.y = scale*(((a0.y + a1.y) + a2.y) + a3.y);
    r.z = scale*(((a0.z + a1.z) + a2.z) + a3.z);
    r.w = scale*(((a0.w + a1.w) + a2.w) + a3.w);
    outp[idx] = r;
}

__global__ void softmax2(float* __restrict__ s,
                         __half* __restrict__ ph, __half* __restrict__ pl,
                         int rows, int L, int ld) {
    int warp = (blockIdx.x*blockDim.x + threadIdx.x) / 32;
    int lane = threadIdx.x % 32;
    if (warp >= rows) return;
    long long ro = (long long)warp * ld;
    float* row = s + ro;
    float mx = -1e30f;
    for (int i = lane; i < L; i += 32) mx = fmaxf(mx, row[i]);
    for (int o = 16; o; o >>= 1) mx = fmaxf(mx, __shfl_xor_sync(0xffffffffu, mx, o));
    float sum = 0.f;
    for (int i = lane; i < L; i += 32) { float e = __expf(row[i]-mx); row[i] = e; sum += e; }
    for (int o = 16; o; o >>= 1) sum += __shfl_xor_sync(0xffffffffu, sum, o);
    float inv = 1.f / sum;
    for (int i = lane; i < ld; i += 32) {
        float v = (i < L) ? row[i]*inv : 0.f;
        __half h, l; cvt1(v, h, l);
        ph[ro + i] = h; pl[ro + i] = l;
    }
}

// x[b][m][:] += bias + sum_h part[(h*8+b)][m][:]
__global__ void attn_reduce_kernel(const float* __restrict__ part,
                                   const float* __restrict__ bias,
                                   float* __restrict__ x) {
    int idx = blockIdx.x*blockDim.x + threadIdx.x;
    const int D4 = DIM/4;
    int total = BATCH*SEQ*D4;
    if (idx >= total) return;
    int d4 = idx % D4;
    int m  = (idx / D4) % SEQ;
    int b  = idx / (D4*SEQ);
    float4 acc = ((float4*)x)[idx];
    float4 bb = ((const float4*)bias)[d4];
    acc.x += bb.x; acc.y += bb.y; acc.z += bb.z; acc.w += bb.w;
#pragma unroll
    for (int h = 0; h < HEADS; h++) {
        float4 p = ((const float4*)part)[((long long)(h*BATCH+b)*SEQ + m)*D4 + d4];
        acc.x += p.x; acc.y += p.y; acc.z += p.z; acc.w += p.w;
    }
    ((float4*)x)[idx] = acc;
}

__global__ void x_to_y2(const float* __restrict__ x, float* __restrict__ y,
                        __half* __restrict__ yh, __half* __restrict__ yl) {
    int idx = blockIdx.x*blockDim.x + threadIdx.x;
    int total = BATCH*CDIM*TDIM;
    if (idx >= total) return;
    int t = idx % TDIM;
    int c = (idx / TDIM) % CDIM;
    int b = idx / (TDIM*CDIM);
    int f = t / SEQ, mm = t % SEQ;
    float v = x[((long long)b*SEQ + mm)*DIM + c*8 + f];
    y[idx] = v;
    __half h, l; cvt1(v, h, l);
    yh[idx] = h; yl[idx] = l;
}

__global__ void y_to_x_kernel(const float* __restrict__ y, float* __restrict__ x) {
    int idx = blockIdx.x*blockDim.x + threadIdx.x;
    int total = BATCH*SEQ*DIM;
    if (idx >= total) return;
    int d  = idx % DIM;
    int mm = (idx / DIM) % SEQ;
    int b  = idx / (DIM*SEQ);
    int c = d >> 3, f = d & 7;
    x[idx] = y[((long long)b*CDIM + c)*TDIM + f*SEQ + mm];
}

__global__ void cls_ln_kernel(const float* __restrict__ x, const float* __restrict__ g,
                              const float* __restrict__ be, float* __restrict__ out) {
    int b = blockIdx.x, t = threadIdx.x;
    const float* row = x + (long long)b*SEQ*DIM;
    __shared__ float red[256];
    float s = 0.f;
    for (int i = t; i < DIM; i += 256) s += row[i];
    red[t] = s; __syncthreads();
    for (int o = 128; o > 0; o >>= 1) { if (t < o) red[t] += red[t+o]; __syncthreads(); }
    float mu = red[0] / DIM; __syncthreads();
    float v = 0.f;
    for (int i = t; i < DIM; i += 256) { float d = row[i]-mu; v += d*d; }
    red[t] = v; __syncthreads();
    for (int o = 128; o > 0; o >>= 1) { if (t < o) red[t] += red[t+o]; __syncthreads(); }
    float inv = rsqrtf(red[0]/DIM + 1e-5f);
    for (int i = t; i < DIM; i += 256) out[b*DIM + i] = (row[i]-mu)*inv*g[i] + be[i];
}

static inline int nblk(long long n, int t) { return (int)((n + t - 1) / t); }

extern "C" void kernel_launch(void* const* d_in, const int* in_sizes, int n_in,
                              void* d_out, int out_size) {
    const float* img       = (const float*)d_in[0];
    const float* patch_W   = (const float*)d_in[1];
    const float* patch_b   = (const float*)d_in[2];
    const float* cls_token = (const float*)d_in[3];
    const float* rms_scale = (const float*)d_in[4];
    const float* Wq        = (const float*)d_in[5];
    const float* Wk        = (const float*)d_in[6];
    const float* Wv        = (const float*)d_in[7];
    const float* attn_W    = (const float*)d_in[8];
    const float* attn_b    = (const float*)d_in[9];
    const float* tWq       = (const float*)d_in[10];
    const float* tWk       = (const float*)d_in[11];
    const float* tWv       = (const float*)d_in[12];
    const float* ln_g      = (const float*)d_in[13];
    const float* ln_b      = (const float*)d_in[14];
    const float* head_W    = (const float*)d_in[15];
    const float* head_b    = (const float*)d_in[16];
    float* out = (float*)d_out;

    float *pxp,*px,*pqkv,*ps,*po,*pot,*py,*ptqkv,*pts,*pts4,*pf,*pred,*pcls;
    float2 *ptab1,*ptab2;
    cudaGetSymbolAddress((void**)&pxp,  g_xp);
    cudaGetSymbolAddress((void**)&px,   g_x);
    cudaGetSymbolAddress((void**)&pqkv, g_qkv);
    cudaGetSymbolAddress((void**)&ps,   g_sc);
    cudaGetSymbolAddress((void**)&po,   g_o);
    cudaGetSymbolAddress((void**)&pot,  g_ot);
    cudaGetSymbolAddress((void**)&py,   g_y);
    cudaGetSymbolAddress((void**)&ptqkv,g_tqkv);
    cudaGetSymbolAddress((void**)&pts,  g_ts);
    cudaGetSymbolAddress((void**)&pts4, g_ts4);
    cudaGetSymbolAddress((void**)&pf,   g_fac);
    cudaGetSymbolAddress((void**)&pred, g_red);
    cudaGetSymbolAddress((void**)&pcls, g_cls);
    cudaGetSymbolAddress((void**)&ptab1, g_tab1);
    cudaGetSymbolAddress((void**)&ptab2, g_tab2);

    __half *path_h,*path_l,*xh,*xl,*qh,*ql,*kh,*ph,*pl,*oh,*ol;
    __half *yh,*yl,*tqh,*tql,*tkh,*tsh,*tsl;
    __half *pwh,*wAh,*awh,*twAh,*vth,*tvth;
    cudaGetSymbolAddress((void**)&path_h, g_path_h); cudaGetSymbolAddress((void**)&path_l, g_path_l);
    cudaGetSymbolAddress((void**)&xh,  g_xh);  cudaGetSymbolAddress((void**)&xl,  g_xl);
    cudaGetSymbolAddress((void**)&qh,  g_qh);  cudaGetSymbolAddress((void**)&ql,  g_ql);
    cudaGetSymbolAddress((void**)&kh,  g_kh);
    cudaGetSymbolAddress((void**)&ph,  g_ph);  cudaGetSymbolAddress((void**)&pl,  g_pl);
    cudaGetSymbolAddress((void**)&oh,  g_oh);  cudaGetSymbolAddress((void**)&ol,  g_ol);
    cudaGetSymbolAddress((void**)&yh,  g_yh);  cudaGetSymbolAddress((void**)&yl,  g_yl);
    cudaGetSymbolAddress((void**)&tqh, g_tqh); cudaGetSymbolAddress((void**)&tql, g_tql);
    cudaGetSymbolAddress((void**)&tkh, g_tkh);
    cudaGetSymbolAddress((void**)&tsh, g_tsh); cudaGetSymbolAddress((void**)&tsl, g_tsl);
    cudaGetSymbolAddress((void**)&pwh,  g_pwh);
    cudaGetSymbolAddress((void**)&wAh,  g_wAh);
    cudaGetSymbolAddress((void**)&awh,  g_awh);
    cudaGetSymbolAddress((void**)&twAh, g_twAh);
    cudaGetSymbolAddress((void**)&vth,  g_vth);
    cudaGetSymbolAddress((void**)&tvth, g_tvth);

    const long long sQH  = (long long)SEQ*DIM;
    const long long sSSp = (long long)SEQ*SEQP;
    const long long sY   = (long long)CDIM*TDIM;
    const long long sYp  = (long long)CDIM*TDIMP;
    const long long sTS  = (long long)CDIM*CDIM;
    const long long sW   = (long long)DIM*DIM;
    const long long sVT  = (long long)DIM*SEQP;
    const long long sTVT = (long long)TDIM*CDIM;
    const long long sTW  = (long long)TDIM*TDIM;
    const float scale1 = (float)(1.0/sqrt(512.0));
    const float scale2 = (float)(1.0/sqrt(1576.0));
    const float cc1 = (float)(-2.0*log2(10000.0)/512.0);
    const float cc2 = (float)(-2.0*log2(10000.0)/1576.0);
    dim3 tcb(32, 8);

    // ---- rope tables ----
    rope_tab<<<nblk(SEQ*256,256),256>>>(ptab1, SEQ, 256, cc1);
    rope_tab<<<nblk(CDIM*788,256),256>>>(ptab2, CDIM, 788, cc2);

    // ---- weight pre-conversion (hi only; weights are GEMM B operands) ----
    tconv<<<dim3(DIM/32, PK/64, 1), tcb>>>(patch_W, pwh, PK, DIM, PK, 0, 0);
    for (int l = 0; l < 2; l++) {
        const float* srcs[3] = {Wq, Wk, Wv};
        for (int w = 0; w < 3; w++) {
            tconv<<<dim3(16, 8, 8), tcb>>>(srcs[w] + (long long)l*8*sW,
                                           wAh + ((long long)l*24 + w*8)*sW,
                                           DIM, DIM, DIM, sW, sW);
        }
        const float* tsrcs[3] = {tWq, tWk, tWv};
        for (int w = 0; w < 3; w++) {
            tconv<<<dim3(50, 25, 1), tcb>>>(tsrcs[w] + (long long)l*sTW,
                                            twAh + ((long long)l*3 + w)*sTW,
                                            TDIM, TDIM, TDIM, 0, 0);
        }
    }
    tconv<<<dim3(16, 8, 16), tcb>>>(attn_W, awh, DIM, DIM, DIM, sW, sW);

    // ---- patch embedding ----
    patch_gather2<<<nblk((long long)BATCH*NPATCH*PK,256),256>>>(img, path_h, path_l);
    run_hgemm(path_h, path_l, pwh, patch_b, 0, pxp, 0, 0,
              BATCH*NPATCH, DIM, PK, PK, PK, DIM,
              P_NONE, P_NONE, 0, 0, 1, 1.f, 0);
    assemble_x_kernel<<<nblk((long long)BATCH*SEQ*DIM,256),256>>>(pxp, cls_token, px);

    for (int l = 0; l < 2; l++) {
        const float* scale_l = rms_scale + (long long)l*SEQ*DIM;

        // rmsnorm #1 (+split)
        rms_part_kernel<<<dim3(32,BATCH),256>>>(px, pred);
        rms_fin_kernel<<<1,256>>>(pred, pf);
        rms_apply2<<<nblk((long long)BATCH*SEQ*DIM/4,256),256>>>(px, pf, scale_l,
                                                                 (uint2*)xh, (uint2*)xl);

        // fused QKV, batch folded into M: M=1576, z = w*8+h (24 batches)
        run_hgemm(xh, xl, wAh + (long long)l*24*sW, 0, 0, pqkv, 0, 0,
                  BATCH*SEQ, DIM, DIM, DIM, DIM, DIM,
                  P_NONE,
                  8, 8*sW, 8, 0LL, sW,
                  0, 8*sQH, 24, 1.f, 0);

        // v -> vT hi [DIM][SEQP]
        tconv<<<dim3(16, 4, 64), tcb>>>(pqkv + 128*sQH, vth, SEQ, DIM, SEQP, sQH, sVT);

        // RoPE -> q hi/lo, k hi
        rope3<<<nblk((long long)64*SEQ*(DIM/2),256),256>>>(pqkv, pqkv + 64*sQH,
                                                           qh, ql, kh, ptab1, 64, SEQ, DIM, DIM);

        // scores
        run_hgemm(qh, ql, kh, 0, 0, ps, 0, 0,
                  SEQ, SEQ, DIM, DIM, DIM, SEQP,
                  P_PLAIN(sQH), P_PLAIN(sQH), 0, sSSp, 64, scale1, 0);
        softmax2<<<nblk((long long)64*SEQ*32,256),256>>>(ps, ph, pl, 64*SEQ, SEQ, SEQP);

        // o = p @ v (epilogue emits split oh/ol)
        run_hgemm(ph, pl, vth, 0, 0, po, oh, ol,
                  SEQ, DIM, SEQP, SEQP, SEQP, DIM,
                  P_PLAIN(sSSp), P_PLAIN(sVT), 0, sQH, 64, 1.f, 0);

        // proj partials, batch folded into M: M=1576, z=h (8 batches)
        run_hgemm(oh, ol, awh + (long long)l*8*sW, 0, 0, pot, 0, 0,
                  BATCH*SEQ, DIM, DIM, DIM, DIM, DIM,
                  P_PLAIN(8*sQH), P_PLAIN(sW), 0, 8*sQH, 8, 1.f, 0);
        attn_reduce_kernel<<<nblk((long long)BATCH*SEQ*DIM/4,256),256>>>(pot, attn_b + l*DIM, px);

        // rmsnorm #2 (+split)
        rms_part_kernel<<<dim3(32,BATCH),256>>>(px, pred);
        rms_fin_kernel<<<1,256>>>(pred, pf);
        rms_apply2<<<nblk((long long)BATCH*SEQ*DIM/4,256),256>>>(px, pf, scale_l,
                                                                 (uint2*)xh, (uint2*)xl);

        // token-mixing
        x_to_y2<<<nblk((long long)BATCH*CDIM*TDIM,256),256>>>(px, py, yh, yl);

        // fused token QKV, batch folded into M: M=512, z=w (3 batches)
        run_hgemm(yh, yl, twAh + (long long)l*3*sTW, 0, 0, ptqkv, 0, 0,
                  BATCH*CDIM, TDIM, TDIM, TDIM, TDIM, TDIM,
                  P_NONE, P_PLAIN(sTW), 0, 8*sY, 3, 1.f, 0);

        // tv -> tvT hi
        tconv<<<dim3(50, 1, 8), tcb>>>(ptqkv + 16*sY, tvth, CDIM, TDIM, CDIM, sY, sTVT);

        // RoPE -> tq hi/lo (padded), tk hi (padded); pad stays zero
        rope3<<<nblk((long long)BATCH*CDIM*(TDIM/2),256),256>>>(ptqkv, ptqkv + 8*sY,
                                                                 tqh, tql, tkh,
                                                                 ptab2, BATCH, CDIM, TDIM, TDIMP);

        // token scores, split-K x4: z = b*4+c -> 32 blocks
        run_hgemm(tqh, tql, tkh, 0, 0, pts4, 0, 0,
                  CDIM, CDIM, 400, TDIMP, TDIMP, CDIM,
                  4, sYp, 1, 400LL, 0LL,
                  4, sYp, 1, 400LL, 0LL,
                  0, sTS, 32, 1.f, 0);
        tsred_kernel<<<nblk((long long)BATCH*CDIM*CDIM/4,256),256>>>((const float4*)pts4,
                                                                     (float4*)pts, scale2);
        softmax2<<<nblk((long long)BATCH*CDIM*32,256),256>>>(pts, tsh, tsl,
                                                             BATCH*CDIM, CDIM, CDIM);

        // y += p @ tv
        run_hgemm(tsh, tsl, tvth, 0, py, py, 0, 0,
                  CDIM, TDIM, CDIM, CDIM, CDIM, TDIM,
                  P_PLAIN(sTS), P_PLAIN(sTVT), sY, sY, BATCH, 1.f, 1);

        y_to_x_kernel<<<nblk((long long)BATCH*SEQ*DIM,256),256>>>(py, px);
    }

    // ---- final: cls layernorm + head ----
    cls_ln_kernel<<<BATCH,256>>>(px, ln_g, ln_b, pcls);
    {
        dim3 grid((NCLS+31)/32, 1, 1);
        sgemm_s<<<grid, 64>>>(pcls, head_W, head_b, out, BATCH, NCLS, DIM, DIM, NCLS, NCLS);
    }
}